// round 6
// baseline (speedup 1.0000x reference)
#include <cuda_runtime.h>
#include <cstdint>
#include <cstddef>

#define MAXN 50000
#define MAXE 800000
#define NF   128
#define NOUT 64

// Scratch (no allocations allowed -> __device__ globals).
__device__ float g_y1[(size_t)MAXN * NF];     // x @ W1^T
__device__ float g_s1[(size_t)MAXN * NF];     // gather-spmm(y1)
__device__ float g_y2[(size_t)MAXN * NOUT];   // relu(s1) @ W2^T
__device__ int   g_deg[MAXN];                 // degree counts, then write-cursor
__device__ int   g_off[MAXN + 1];             // CSR row offsets (by dst)
__device__ int2  g_edges[MAXE];               // packed {src, __float_as_int(val)} by dst

// ---------------------------------------------------------------------------
// CSR build: histogram -> single-block scan -> permute
// ---------------------------------------------------------------------------
__global__ void hist_kernel(const int* __restrict__ dst, int E) {
    int i = blockIdx.x * blockDim.x + threadIdx.x;
    if (i < E) atomicAdd(&g_deg[__ldg(dst + i)], 1);
}

// One block, 1024 threads: exclusive scan of g_deg[0..n) into g_off (+cursor copy).
__global__ __launch_bounds__(1024) void scan_all_kernel(int n, int E) {
    __shared__ int wsum[32];
    const int t     = threadIdx.x;
    const int lane  = t & 31;
    const int wid   = t >> 5;
    const int chunk = (n + 1023) >> 10;
    const int beg   = t * chunk;
    const int end   = (beg + chunk < n) ? beg + chunk : n;

    int sum = 0;
    for (int i = beg; i < end; ++i) sum += g_deg[i];

    // inclusive warp scan of per-thread sums
    int v = sum;
#pragma unroll
    for (int o = 1; o < 32; o <<= 1) {
        int u = __shfl_up_sync(0xffffffffu, v, o);
        if (lane >= o) v += u;
    }
    if (lane == 31) wsum[wid] = v;
    __syncthreads();
    if (wid == 0) {
        int w = wsum[lane];
#pragma unroll
        for (int o = 1; o < 32; o <<= 1) {
            int u = __shfl_up_sync(0xffffffffu, w, o);
            if (lane >= o) w += u;
        }
        wsum[lane] = w;
    }
    __syncthreads();

    int run = v - sum + (wid ? wsum[wid - 1] : 0);   // exclusive prefix for this thread
    for (int i = beg; i < end; ++i) {
        int d = g_deg[i];
        g_off[i] = run;
        g_deg[i] = run;                               // reuse deg[] as write cursor
        run += d;
    }
    if (t == 0) g_off[n] = E;
}

__global__ void permute_kernel(const int* __restrict__ src, const int* __restrict__ dst,
                               const float* __restrict__ vals, int E) {
    int e = blockIdx.x * blockDim.x + threadIdx.x;
    if (e >= E) return;
    int pos = atomicAdd(&g_deg[__ldg(dst + e)], 1);
    g_edges[pos] = make_int2(__ldg(src + e), __float_as_int(__ldg(vals + e)));
}

// ---------------------------------------------------------------------------
// tf32 helpers
// ---------------------------------------------------------------------------
__device__ __forceinline__ uint32_t f2tf32(float x) {
    uint32_t r;
    asm("cvt.rna.tf32.f32 %0, %1;" : "=r"(r) : "f"(x));
    return r;
}

__device__ __forceinline__ void mma_tf32(float* d, const uint32_t* a, uint32_t b0, uint32_t b1) {
    asm volatile(
        "mma.sync.aligned.m16n8k8.row.col.f32.tf32.tf32.f32 "
        "{%0,%1,%2,%3}, {%4,%5,%6,%7}, {%8,%9}, {%0,%1,%2,%3};"
        : "+f"(d[0]), "+f"(d[1]), "+f"(d[2]), "+f"(d[3])
        : "r"(a[0]), "r"(a[1]), "r"(a[2]), "r"(a[3]), "r"(b0), "r"(b1));
}

// ---------------------------------------------------------------------------
// C[M, NCOLS] = act(A)[M, 128] @ W[NCOLS, 128]^T via 3xTF32 tensor-core MMA.
// BM=128, BK=16, 256 threads (8 warps, 4x2 warp grid; warp tile m32 x NCOLS/2).
// hi/lo split once at staging; error ~2^-22 per product -> fp32-level accuracy.
// ---------------------------------------------------------------------------
template <int NCOLS, bool RELU_IN>
__global__ __launch_bounds__(256) void gemm_tc_kernel(
    const float* __restrict__ A, const float* __restrict__ W,
    float* __restrict__ C, int M)
{
    constexpr int BK   = 16;
    constexpr int APAD = 132;
    constexpr int BPAD = NCOLS + 4;
    constexpr int NT   = NCOLS / 16;

    __shared__ uint32_t As_hi[BK * APAD];
    __shared__ uint32_t As_lo[BK * APAD];
    __shared__ uint32_t Bs_hi[BK * BPAD];
    __shared__ uint32_t Bs_lo[BK * BPAD];

    const int tid  = threadIdx.x;
    const int wid  = tid >> 5;
    const int lane = tid & 31;
    const int g    = lane >> 2;
    const int t    = lane & 3;
    const int warp_m = wid >> 1;
    const int warp_n = wid & 1;
    const int blockRow = blockIdx.x * 128;

    float acc[2][NT][4];
#pragma unroll
    for (int mt = 0; mt < 2; ++mt)
#pragma unroll
        for (int nt = 0; nt < NT; ++nt)
#pragma unroll
            for (int i = 0; i < 4; ++i) acc[mt][nt][i] = 0.f;

    const int  arow  = tid >> 1;
    const int  akoff = (tid & 1) * 8;
    const int  gArow = blockRow + arow;
    const bool aok   = (gArow < M);

    for (int k0 = 0; k0 < 128; k0 += BK) {
        // ---- stage A (with optional relu), split hi/lo ----
        {
            float4 v0 = make_float4(0.f, 0.f, 0.f, 0.f);
            float4 v1 = make_float4(0.f, 0.f, 0.f, 0.f);
            if (aok) {
                v0 = *reinterpret_cast<const float4*>(A + (size_t)gArow * 128 + k0 + akoff);
                v1 = *reinterpret_cast<const float4*>(A + (size_t)gArow * 128 + k0 + akoff + 4);
            }
            float vv[8] = {v0.x, v0.y, v0.z, v0.w, v1.x, v1.y, v1.z, v1.w};
#pragma unroll
            for (int j = 0; j < 8; ++j) {
                float f = RELU_IN ? fmaxf(vv[j], 0.f) : vv[j];
                uint32_t hi = f2tf32(f);
                uint32_t lo = f2tf32(f - __uint_as_float(hi));
                As_hi[(akoff + j) * APAD + arow] = hi;
                As_lo[(akoff + j) * APAD + arow] = lo;
            }
        }
        // ---- stage W, split hi/lo ----
        if (NCOLS == 128) {
            int brow  = tid >> 1;
            int bkoff = (tid & 1) * 8;
            float4 v0 = *reinterpret_cast<const float4*>(W + (size_t)brow * 128 + k0 + bkoff);
            float4 v1 = *reinterpret_cast<const float4*>(W + (size_t)brow * 128 + k0 + bkoff + 4);
            float vv[8] = {v0.x, v0.y, v0.z, v0.w, v1.x, v1.y, v1.z, v1.w};
#pragma unroll
            for (int j = 0; j < 8; ++j) {
                uint32_t hi = f2tf32(vv[j]);
                uint32_t lo = f2tf32(vv[j] - __uint_as_float(hi));
                Bs_hi[(bkoff + j) * BPAD + brow] = hi;
                Bs_lo[(bkoff + j) * BPAD + brow] = lo;
            }
        } else {
            int brow  = tid >> 2;
            int bkoff = (tid & 3) * 4;
            float4 v = *reinterpret_cast<const float4*>(W + (size_t)brow * 128 + k0 + bkoff);
            float vv[4] = {v.x, v.y, v.z, v.w};
#pragma unroll
            for (int j = 0; j < 4; ++j) {
                uint32_t hi = f2tf32(vv[j]);
                uint32_t lo = f2tf32(vv[j] - __uint_as_float(hi));
                Bs_hi[(bkoff + j) * BPAD + brow] = hi;
                Bs_lo[(bkoff + j) * BPAD + brow] = lo;
            }
        }
        __syncthreads();

        // ---- 2 mma k-steps per staged tile ----
#pragma unroll
        for (int ks = 0; ks < 2; ++ks) {
            const int kb = ks * 8;
            uint32_t a_hi[2][4], a_lo[2][4];
#pragma unroll
            for (int mt = 0; mt < 2; ++mt) {
                int mrow = warp_m * 32 + mt * 16 + g;
                a_hi[mt][0] = As_hi[(kb + t) * APAD + mrow];
                a_hi[mt][1] = As_hi[(kb + t) * APAD + mrow + 8];
                a_hi[mt][2] = As_hi[(kb + t + 4) * APAD + mrow];
                a_hi[mt][3] = As_hi[(kb + t + 4) * APAD + mrow + 8];
                a_lo[mt][0] = As_lo[(kb + t) * APAD + mrow];
                a_lo[mt][1] = As_lo[(kb + t) * APAD + mrow + 8];
                a_lo[mt][2] = As_lo[(kb + t + 4) * APAD + mrow];
                a_lo[mt][3] = As_lo[(kb + t + 4) * APAD + mrow + 8];
            }
#pragma unroll
            for (int nt = 0; nt < NT; ++nt) {
                int ncol = warp_n * (NCOLS / 2) + nt * 8 + g;
                uint32_t b_hi0 = Bs_hi[(kb + t) * BPAD + ncol];
                uint32_t b_hi1 = Bs_hi[(kb + t + 4) * BPAD + ncol];
                uint32_t b_lo0 = Bs_lo[(kb + t) * BPAD + ncol];
                uint32_t b_lo1 = Bs_lo[(kb + t + 4) * BPAD + ncol];
#pragma unroll
                for (int mt = 0; mt < 2; ++mt) {
                    mma_tf32(acc[mt][nt], a_hi[mt], b_hi0, b_hi1);
                    mma_tf32(acc[mt][nt], a_hi[mt], b_lo0, b_lo1);
                    mma_tf32(acc[mt][nt], a_lo[mt], b_hi0, b_hi1);
                }
            }
        }
        __syncthreads();
    }

    // ---- store C ----
#pragma unroll
    for (int mt = 0; mt < 2; ++mt) {
#pragma unroll
        for (int half = 0; half < 2; ++half) {
            int row = blockRow + warp_m * 32 + mt * 16 + half * 8 + g;
            if (row < M) {
#pragma unroll
                for (int nt = 0; nt < NT; ++nt) {
                    int col = warp_n * (NCOLS / 2) + nt * 8 + 2 * t;
                    float2 o = make_float2(acc[mt][nt][half * 2], acc[mt][nt][half * 2 + 1]);
                    *reinterpret_cast<float2*>(C + (size_t)row * NCOLS + col) = o;
                }
            }
        }
    }
}

// ---------------------------------------------------------------------------
// Gather SPMM, 128-wide: one warp per dst node, 4-edge unroll for MLP.
// ---------------------------------------------------------------------------
__global__ __launch_bounds__(256) void gather128_kernel(
    const float* __restrict__ Y, float* __restrict__ S, int n)
{
    int gid  = blockIdx.x * blockDim.x + threadIdx.x;
    int d    = gid >> 5;
    int lane = threadIdx.x & 31;
    if (d >= n) return;
    int beg = g_off[d], end = g_off[d + 1];

    float4 acc = make_float4(0.f, 0.f, 0.f, 0.f);
    int e = beg;
    for (; e + 3 < end; e += 4) {
        int2 p0 = __ldg(&g_edges[e]);
        int2 p1 = __ldg(&g_edges[e + 1]);
        int2 p2 = __ldg(&g_edges[e + 2]);
        int2 p3 = __ldg(&g_edges[e + 3]);
        float4 f0 = *reinterpret_cast<const float4*>(Y + (size_t)p0.x * 128 + lane * 4);
        float4 f1 = *reinterpret_cast<const float4*>(Y + (size_t)p1.x * 128 + lane * 4);
        float4 f2 = *reinterpret_cast<const float4*>(Y + (size_t)p2.x * 128 + lane * 4);
        float4 f3 = *reinterpret_cast<const float4*>(Y + (size_t)p3.x * 128 + lane * 4);
        float v0 = __int_as_float(p0.y), v1 = __int_as_float(p1.y);
        float v2 = __int_as_float(p2.y), v3 = __int_as_float(p3.y);
        acc.x = fmaf(v0, f0.x, acc.x); acc.y = fmaf(v0, f0.y, acc.y);
        acc.z = fmaf(v0, f0.z, acc.z); acc.w = fmaf(v0, f0.w, acc.w);
        acc.x = fmaf(v1, f1.x, acc.x); acc.y = fmaf(v1, f1.y, acc.y);
        acc.z = fmaf(v1, f1.z, acc.z); acc.w = fmaf(v1, f1.w, acc.w);
        acc.x = fmaf(v2, f2.x, acc.x); acc.y = fmaf(v2, f2.y, acc.y);
        acc.z = fmaf(v2, f2.z, acc.z); acc.w = fmaf(v2, f2.w, acc.w);
        acc.x = fmaf(v3, f3.x, acc.x); acc.y = fmaf(v3, f3.y, acc.y);
        acc.z = fmaf(v3, f3.z, acc.z); acc.w = fmaf(v3, f3.w, acc.w);
    }
    for (; e < end; ++e) {
        int2 p = __ldg(&g_edges[e]);
        float v = __int_as_float(p.y);
        float4 f = *reinterpret_cast<const float4*>(Y + (size_t)p.x * 128 + lane * 4);
        acc.x = fmaf(v, f.x, acc.x); acc.y = fmaf(v, f.y, acc.y);
        acc.z = fmaf(v, f.z, acc.z); acc.w = fmaf(v, f.w, acc.w);
    }
    *reinterpret_cast<float4*>(S + (size_t)d * 128 + lane * 4) = acc;
}

// ---------------------------------------------------------------------------
// Gather SPMM, 64-wide, fused with row softmax: warp per node, 2 floats/lane.
// ---------------------------------------------------------------------------
__global__ __launch_bounds__(256) void gather64_softmax_kernel(
    const float* __restrict__ Y, float* __restrict__ out, int n)
{
    int gid  = blockIdx.x * blockDim.x + threadIdx.x;
    int d    = gid >> 5;
    int lane = threadIdx.x & 31;
    if (d >= n) return;
    int beg = g_off[d], end = g_off[d + 1];

    float2 acc = make_float2(0.f, 0.f);
    int e = beg;
    for (; e + 3 < end; e += 4) {
        int2 p0 = __ldg(&g_edges[e]);
        int2 p1 = __ldg(&g_edges[e + 1]);
        int2 p2 = __ldg(&g_edges[e + 2]);
        int2 p3 = __ldg(&g_edges[e + 3]);
        float2 f0 = *reinterpret_cast<const float2*>(Y + (size_t)p0.x * 64 + lane * 2);
        float2 f1 = *reinterpret_cast<const float2*>(Y + (size_t)p1.x * 64 + lane * 2);
        float2 f2 = *reinterpret_cast<const float2*>(Y + (size_t)p2.x * 64 + lane * 2);
        float2 f3 = *reinterpret_cast<const float2*>(Y + (size_t)p3.x * 64 + lane * 2);
        float v0 = __int_as_float(p0.y), v1 = __int_as_float(p1.y);
        float v2 = __int_as_float(p2.y), v3 = __int_as_float(p3.y);
        acc.x = fmaf(v0, f0.x, acc.x); acc.y = fmaf(v0, f0.y, acc.y);
        acc.x = fmaf(v1, f1.x, acc.x); acc.y = fmaf(v1, f1.y, acc.y);
        acc.x = fmaf(v2, f2.x, acc.x); acc.y = fmaf(v2, f2.y, acc.y);
        acc.x = fmaf(v3, f3.x, acc.x); acc.y = fmaf(v3, f3.y, acc.y);
    }
    for (; e < end; ++e) {
        int2 p = __ldg(&g_edges[e]);
        float v = __int_as_float(p.y);
        float2 f = *reinterpret_cast<const float2*>(Y + (size_t)p.x * 64 + lane * 2);
        acc.x = fmaf(v, f.x, acc.x); acc.y = fmaf(v, f.y, acc.y);
    }

    // warp softmax over the 64-value row (2 per lane)
    float m = fmaxf(acc.x, acc.y);
#pragma unroll
    for (int o = 16; o; o >>= 1) m = fmaxf(m, __shfl_xor_sync(0xffffffffu, m, o));
    float e0 = __expf(acc.x - m);
    float e1 = __expf(acc.y - m);
    float ssum = e0 + e1;
#pragma unroll
    for (int o = 16; o; o >>= 1) ssum += __shfl_xor_sync(0xffffffffu, ssum, o);
    float inv = 1.f / ssum;
    *reinterpret_cast<float2*>(out + (size_t)d * 64 + lane * 2) =
        make_float2(e0 * inv, e1 * inv);
}

// ---------------------------------------------------------------------------
// Launch. Inputs: x, vals, W1, W2, src, dst. Output fp32 [N, 64].
// ---------------------------------------------------------------------------
extern "C" void kernel_launch(void* const* d_in, const int* in_sizes, int n_in,
                              void* d_out, int out_size)
{
    const float* x    = (const float*)d_in[0];
    const float* vals = (const float*)d_in[1];
    const float* W1   = (const float*)d_in[2];
    const float* W2   = (const float*)d_in[3];
    const int*   src  = (const int*)d_in[4];
    const int*   dst  = (const int*)d_in[5];
    float*       out  = (float*)d_out;

    const int M = in_sizes[0] / NF;   // 50000
    const int E = in_sizes[1];        // 800000

    float *y1, *s1, *y2;
    int* degp;
    cudaGetSymbolAddress((void**)&y1, g_y1);
    cudaGetSymbolAddress((void**)&s1, g_s1);
    cudaGetSymbolAddress((void**)&y2, g_y2);
    cudaGetSymbolAddress((void**)&degp, g_deg);

    // --- CSR build (by dst) ---
    cudaMemsetAsync(degp, 0, M * sizeof(int));
    hist_kernel<<<(E + 255) / 256, 256>>>(dst, E);
    scan_all_kernel<<<1, 1024>>>(M, E);
    permute_kernel<<<(E + 255) / 256, 256>>>(src, dst, vals, E);

    // --- pipeline ---
    int gemmBlocks = (M + 127) / 128;
    gemm_tc_kernel<128, false><<<gemmBlocks, 256>>>(x, W1, y1, M);          // y1 = x @ W1^T
    gather128_kernel<<<(M * 32 + 255) / 256, 256>>>(y1, s1, M);             // s1 = A @ y1
    gemm_tc_kernel<64, true><<<gemmBlocks, 256>>>(s1, W2, y2, M);           // y2 = relu(s1) @ W2^T
    gather64_softmax_kernel<<<(M * 32 + 255) / 256, 256>>>(y2, out, M);     // out = softmax(A @ y2)
}

// round 9
// speedup vs baseline: 1.4859x; 1.4859x over previous
#include <cuda_runtime.h>
#include <cstdint>
#include <cstddef>

#define MAXN 50000
#define MAXE 800000
#define NF   128
#define NOUT 64
#define SCAN_B 512

// Scratch (no allocations allowed -> __device__ globals).
__device__ float g_y1[(size_t)MAXN * NF];     // x @ W1^T
__device__ float g_s1[(size_t)MAXN * NF];     // gather-spmm(y1)
__device__ float g_y2[(size_t)MAXN * NOUT];   // relu(s1) @ W2^T
__device__ int   g_deg[MAXN];                 // degree counts, then write-cursor
__device__ int   g_off[MAXN + 1];             // CSR row offsets (by dst)
__device__ int   g_bsum[SCAN_B];              // scan block sums
__device__ int2  g_edges[MAXE];               // packed {src, __float_as_int(val)} by dst

// ---------------------------------------------------------------------------
// CSR build: histogram -> scan1 (per-block) -> scan23 (apply) -> permute
// ---------------------------------------------------------------------------
__global__ void hist_kernel(const int* __restrict__ dst, int E) {
    int i = blockIdx.x * blockDim.x + threadIdx.x;
    if (i < E) atomicAdd(&g_deg[__ldg(dst + i)], 1);
}

__global__ __launch_bounds__(SCAN_B) void scan1_kernel(int n) {
    __shared__ int sh[SCAN_B];
    int t = threadIdx.x;
    int i = blockIdx.x * SCAN_B + t;
    int v = (i < n) ? g_deg[i] : 0;
    sh[t] = v;
    __syncthreads();
#pragma unroll
    for (int o = 1; o < SCAN_B; o <<= 1) {
        int u = (t >= o) ? sh[t - o] : 0;
        __syncthreads();
        sh[t] += u;
        __syncthreads();
    }
    if (i <= n && i < MAXN + 1) g_off[i] = sh[t] - v;   // block-local exclusive
    if (t == SCAN_B - 1) g_bsum[blockIdx.x] = sh[t];
}

// Each block: thread 0 scans the nb block sums into smem; all threads apply.
__global__ void scan23_kernel(int n, int nb, int E) {
    __shared__ int pref[256];            // nb <= 98
    int t = threadIdx.x;
    if (t == 0) {
        int run = 0;
        for (int b = 0; b < nb; ++b) { pref[b] = run; run += g_bsum[b]; }
    }
    __syncthreads();
    int i = blockIdx.x * blockDim.x + t;
    if (i < n) {
        int o = g_off[i] + pref[i >> 9];
        g_off[i] = o;
        g_deg[i] = o;                                   // reuse deg[] as write cursor
    }
    if (i == 0) g_off[n] = E;
}

__global__ void permute_kernel(const int* __restrict__ src, const int* __restrict__ dst,
                               const float* __restrict__ vals, int E) {
    int e = blockIdx.x * blockDim.x + threadIdx.x;
    if (e >= E) return;
    int pos = atomicAdd(&g_deg[__ldg(dst + e)], 1);
    g_edges[pos] = make_int2(__ldg(src + e), __float_as_int(__ldg(vals + e)));
}

// ---------------------------------------------------------------------------
// tf32 / mma / ldmatrix helpers
// ---------------------------------------------------------------------------
__device__ __forceinline__ uint32_t f2tf32(float x) {
    uint32_t r;
    asm("cvt.rna.tf32.f32 %0, %1;" : "=r"(r) : "f"(x));
    return r;
}

__device__ __forceinline__ void mma_tf32(float* d, const uint32_t* a, uint32_t b0, uint32_t b1) {
    asm volatile(
        "mma.sync.aligned.m16n8k8.row.col.f32.tf32.tf32.f32 "
        "{%0,%1,%2,%3}, {%4,%5,%6,%7}, {%8,%9}, {%0,%1,%2,%3};"
        : "+f"(d[0]), "+f"(d[1]), "+f"(d[2]), "+f"(d[3])
        : "r"(a[0]), "r"(a[1]), "r"(a[2]), "r"(a[3]), "r"(b0), "r"(b1));
}

__device__ __forceinline__ void ldm_x4(uint32_t* r, uint32_t saddr) {
    asm volatile("ldmatrix.sync.aligned.m8n8.x4.shared.b16 {%0,%1,%2,%3}, [%4];"
                 : "=r"(r[0]), "=r"(r[1]), "=r"(r[2]), "=r"(r[3]) : "r"(saddr));
}

// ---------------------------------------------------------------------------
// C[M, NCOLS] = act(A)[M, 128] @ W[NCOLS, 128]^T via 3xTF32 tensor-core MMA.
// BM=128, BK=16, 256 threads (8 warps, 4x2 warp grid; warp tile m32 x NCOLS/2).
// A staged [m][k] and W staged [n][k] with 20-word row stride (conflict-free
// ldmatrix phases); fragments loaded via ldmatrix.x4 (4x fewer LDS).
// hi/lo tf32 split at staging -> fp32-level accuracy (3 MMAs).
// ---------------------------------------------------------------------------
template <int NCOLS, bool RELU_IN>
__global__ __launch_bounds__(256) void gemm_tc_kernel(
    const float* __restrict__ A, const float* __restrict__ W,
    float* __restrict__ C, int M)
{
    constexpr int BK   = 16;
    constexpr int STRD = 20;             // words per staged row (16 data + 4 pad)
    constexpr int NT   = NCOLS / 16;     // n-tiles per warp (8 or 4)

    __shared__ uint32_t As_hi[128 * STRD];
    __shared__ uint32_t As_lo[128 * STRD];
    __shared__ uint32_t Bs_hi[NCOLS * STRD];
    __shared__ uint32_t Bs_lo[NCOLS * STRD];

    const int tid  = threadIdx.x;
    const int wid  = tid >> 5;
    const int lane = tid & 31;
    const int g    = lane >> 2;
    const int t    = lane & 3;
    const int warp_m = wid >> 1;          // 0..3
    const int warp_n = wid & 1;           // 0..1
    const int blockRow = blockIdx.x * 128;

    float acc[2][NT][4];
#pragma unroll
    for (int mt = 0; mt < 2; ++mt)
#pragma unroll
        for (int nt = 0; nt < NT; ++nt)
#pragma unroll
            for (int i = 0; i < 4; ++i) acc[mt][nt][i] = 0.f;

    const uint32_t sAhi = (uint32_t)__cvta_generic_to_shared(As_hi);
    const uint32_t sAlo = (uint32_t)__cvta_generic_to_shared(As_lo);
    const uint32_t sBhi = (uint32_t)__cvta_generic_to_shared(Bs_hi);
    const uint32_t sBlo = (uint32_t)__cvta_generic_to_shared(Bs_lo);

    // A staging: 2 threads/row, 8 k each.
    const int  arow  = tid >> 1;
    const int  akoff = (tid & 1) * 8;
    const int  gArow = blockRow + arow;
    const bool aok   = (gArow < M);

    // ldmatrix lane addressing:
    // A tile (m16 x k8): lanes0-15 -> m-rows, k lo half; lanes16-31 -> k hi half.
    const int a_lr = lane & 15;
    const int a_lk = (lane >> 4) * 4;
    // B tile (n16 x k8): lanes0-7 n-lo/k-lo, 8-15 n-lo/k-hi, 16-23 n-hi/k-lo, 24-31 n-hi/k-hi.
    const int b_lr = (lane & 7) + ((lane >> 4) << 3);
    const int b_lk = ((lane >> 3) & 1) * 4;

    for (int k0 = 0; k0 < 128; k0 += BK) {
        // ---- stage A rows [m][k], hi/lo split ----
        {
            float4 v0 = make_float4(0.f, 0.f, 0.f, 0.f);
            float4 v1 = make_float4(0.f, 0.f, 0.f, 0.f);
            if (aok) {
                v0 = *reinterpret_cast<const float4*>(A + (size_t)gArow * 128 + k0 + akoff);
                v1 = *reinterpret_cast<const float4*>(A + (size_t)gArow * 128 + k0 + akoff + 4);
            }
            float vv[8] = {v0.x, v0.y, v0.z, v0.w, v1.x, v1.y, v1.z, v1.w};
            uint32_t hi[8], lo[8];
#pragma unroll
            for (int j = 0; j < 8; ++j) {
                float f = RELU_IN ? fmaxf(vv[j], 0.f) : vv[j];
                hi[j] = f2tf32(f);
                lo[j] = f2tf32(f - __uint_as_float(hi[j]));
            }
            uint32_t* ph = &As_hi[arow * STRD + akoff];
            uint32_t* pl = &As_lo[arow * STRD + akoff];
            *reinterpret_cast<uint4*>(ph)     = make_uint4(hi[0], hi[1], hi[2], hi[3]);
            *reinterpret_cast<uint4*>(ph + 4) = make_uint4(hi[4], hi[5], hi[6], hi[7]);
            *reinterpret_cast<uint4*>(pl)     = make_uint4(lo[0], lo[1], lo[2], lo[3]);
            *reinterpret_cast<uint4*>(pl + 4) = make_uint4(lo[4], lo[5], lo[6], lo[7]);
        }
        // ---- stage W rows [n][k], hi/lo split ----
        if (NCOLS == 128) {
            int brow  = tid >> 1;
            int bkoff = (tid & 1) * 8;
            float4 v0 = *reinterpret_cast<const float4*>(W + (size_t)brow * 128 + k0 + bkoff);
            float4 v1 = *reinterpret_cast<const float4*>(W + (size_t)brow * 128 + k0 + bkoff + 4);
            float vv[8] = {v0.x, v0.y, v0.z, v0.w, v1.x, v1.y, v1.z, v1.w};
            uint32_t hi[8], lo[8];
#pragma unroll
            for (int j = 0; j < 8; ++j) {
                hi[j] = f2tf32(vv[j]);
                lo[j] = f2tf32(vv[j] - __uint_as_float(hi[j]));
            }
            uint32_t* ph = &Bs_hi[brow * STRD + bkoff];
            uint32_t* pl = &Bs_lo[brow * STRD + bkoff];
            *reinterpret_cast<uint4*>(ph)     = make_uint4(hi[0], hi[1], hi[2], hi[3]);
            *reinterpret_cast<uint4*>(ph + 4) = make_uint4(hi[4], hi[5], hi[6], hi[7]);
            *reinterpret_cast<uint4*>(pl)     = make_uint4(lo[0], lo[1], lo[2], lo[3]);
            *reinterpret_cast<uint4*>(pl + 4) = make_uint4(lo[4], lo[5], lo[6], lo[7]);
        } else {
            int brow  = tid >> 2;                // 0..63
            int bkoff = (tid & 3) * 4;
            float4 v = *reinterpret_cast<const float4*>(W + (size_t)brow * 128 + k0 + bkoff);
            float vv[4] = {v.x, v.y, v.z, v.w};
            uint32_t hi[4], lo[4];
#pragma unroll
            for (int j = 0; j < 4; ++j) {
                hi[j] = f2tf32(vv[j]);
                lo[j] = f2tf32(vv[j] - __uint_as_float(hi[j]));
            }
            *reinterpret_cast<uint4*>(&Bs_hi[brow * STRD + bkoff]) = make_uint4(hi[0], hi[1], hi[2], hi[3]);
            *reinterpret_cast<uint4*>(&Bs_lo[brow * STRD + bkoff]) = make_uint4(lo[0], lo[1], lo[2], lo[3]);
        }
        __syncthreads();

        // ---- 2 mma k-steps per staged tile ----
#pragma unroll
        for (int ks = 0; ks < 2; ++ks) {
            const int kb = ks * 8;
            uint32_t ah[2][4], al[2][4];
#pragma unroll
            for (int mt = 0; mt < 2; ++mt) {
                int mrow = warp_m * 32 + mt * 16 + a_lr;
                uint32_t off = (uint32_t)(mrow * STRD + kb + a_lk) * 4u;
                ldm_x4(ah[mt], sAhi + off);
                ldm_x4(al[mt], sAlo + off);
            }
#pragma unroll
            for (int ntp = 0; ntp < NT / 2; ++ntp) {
                int nbase = warp_n * (NCOLS / 2) + ntp * 16;
                uint32_t off = (uint32_t)((nbase + b_lr) * STRD + kb + b_lk) * 4u;
                uint32_t bh[4], bl[4];
                ldm_x4(bh, sBhi + off);
                ldm_x4(bl, sBlo + off);
#pragma unroll
                for (int mt = 0; mt < 2; ++mt) {
                    mma_tf32(acc[mt][2 * ntp],     ah[mt], bh[0], bh[1]);
                    mma_tf32(acc[mt][2 * ntp],     ah[mt], bl[0], bl[1]);
                    mma_tf32(acc[mt][2 * ntp],     al[mt], bh[0], bh[1]);
                    mma_tf32(acc[mt][2 * ntp + 1], ah[mt], bh[2], bh[3]);
                    mma_tf32(acc[mt][2 * ntp + 1], ah[mt], bl[2], bl[3]);
                    mma_tf32(acc[mt][2 * ntp + 1], al[mt], bh[2], bh[3]);
                }
            }
        }
        __syncthreads();
    }

    // ---- store C ----
#pragma unroll
    for (int mt = 0; mt < 2; ++mt) {
#pragma unroll
        for (int half = 0; half < 2; ++half) {
            int row = blockRow + warp_m * 32 + mt * 16 + half * 8 + g;
            if (row < M) {
#pragma unroll
                for (int nt = 0; nt < NT; ++nt) {
                    int col = warp_n * (NCOLS / 2) + nt * 8 + 2 * t;
                    float2 o = make_float2(acc[mt][nt][half * 2], acc[mt][nt][half * 2 + 1]);
                    *reinterpret_cast<float2*>(C + (size_t)row * NCOLS + col) = o;
                }
            }
        }
    }
}

// ---------------------------------------------------------------------------
// Gather SPMM, 128-wide: one warp per dst node, 4-edge unroll for MLP.
// ---------------------------------------------------------------------------
__global__ __launch_bounds__(256) void gather128_kernel(
    const float* __restrict__ Y, float* __restrict__ S, int n)
{
    int gid  = blockIdx.x * blockDim.x + threadIdx.x;
    int d    = gid >> 5;
    int lane = threadIdx.x & 31;
    if (d >= n) return;
    int beg = g_off[d], end = g_off[d + 1];

    float4 acc = make_float4(0.f, 0.f, 0.f, 0.f);
    int e = beg;
    for (; e + 3 < end; e += 4) {
        int2 p0 = __ldg(&g_edges[e]);
        int2 p1 = __ldg(&g_edges[e + 1]);
        int2 p2 = __ldg(&g_edges[e + 2]);
        int2 p3 = __ldg(&g_edges[e + 3]);
        float4 f0 = *reinterpret_cast<const float4*>(Y + (size_t)p0.x * 128 + lane * 4);
        float4 f1 = *reinterpret_cast<const float4*>(Y + (size_t)p1.x * 128 + lane * 4);
        float4 f2 = *reinterpret_cast<const float4*>(Y + (size_t)p2.x * 128 + lane * 4);
        float4 f3 = *reinterpret_cast<const float4*>(Y + (size_t)p3.x * 128 + lane * 4);
        float v0 = __int_as_float(p0.y), v1 = __int_as_float(p1.y);
        float v2 = __int_as_float(p2.y), v3 = __int_as_float(p3.y);
        acc.x = fmaf(v0, f0.x, acc.x); acc.y = fmaf(v0, f0.y, acc.y);
        acc.z = fmaf(v0, f0.z, acc.z); acc.w = fmaf(v0, f0.w, acc.w);
        acc.x = fmaf(v1, f1.x, acc.x); acc.y = fmaf(v1, f1.y, acc.y);
        acc.z = fmaf(v1, f1.z, acc.z); acc.w = fmaf(v1, f1.w, acc.w);
        acc.x = fmaf(v2, f2.x, acc.x); acc.y = fmaf(v2, f2.y, acc.y);
        acc.z = fmaf(v2, f2.z, acc.z); acc.w = fmaf(v2, f2.w, acc.w);
        acc.x = fmaf(v3, f3.x, acc.x); acc.y = fmaf(v3, f3.y, acc.y);
        acc.z = fmaf(v3, f3.z, acc.z); acc.w = fmaf(v3, f3.w, acc.w);
    }
    for (; e < end; ++e) {
        int2 p = __ldg(&g_edges[e]);
        float v = __int_as_float(p.y);
        float4 f = *reinterpret_cast<const float4*>(Y + (size_t)p.x * 128 + lane * 4);
        acc.x = fmaf(v, f.x, acc.x); acc.y = fmaf(v, f.y, acc.y);
        acc.z = fmaf(v, f.z, acc.z); acc.w = fmaf(v, f.w, acc.w);
    }
    *reinterpret_cast<float4*>(S + (size_t)d * 128 + lane * 4) = acc;
}

// ---------------------------------------------------------------------------
// Gather SPMM, 64-wide, fused with row softmax: warp per node, 2 floats/lane.
// ---------------------------------------------------------------------------
__global__ __launch_bounds__(256) void gather64_softmax_kernel(
    const float* __restrict__ Y, float* __restrict__ out, int n)
{
    int gid  = blockIdx.x * blockDim.x + threadIdx.x;
    int d    = gid >> 5;
    int lane = threadIdx.x & 31;
    if (d >= n) return;
    int beg = g_off[d], end = g_off[d + 1];

    float2 acc = make_float2(0.f, 0.f);
    int e = beg;
    for (; e + 3 < end; e += 4) {
        int2 p0 = __ldg(&g_edges[e]);
        int2 p1 = __ldg(&g_edges[e + 1]);
        int2 p2 = __ldg(&g_edges[e + 2]);
        int2 p3 = __ldg(&g_edges[e + 3]);
        float2 f0 = *reinterpret_cast<const float2*>(Y + (size_t)p0.x * 64 + lane * 2);
        float2 f1 = *reinterpret_cast<const float2*>(Y + (size_t)p1.x * 64 + lane * 2);
        float2 f2 = *reinterpret_cast<const float2*>(Y + (size_t)p2.x * 64 + lane * 2);
        float2 f3 = *reinterpret_cast<const float2*>(Y + (size_t)p3.x * 64 + lane * 2);
        float v0 = __int_as_float(p0.y), v1 = __int_as_float(p1.y);
        float v2 = __int_as_float(p2.y), v3 = __int_as_float(p3.y);
        acc.x = fmaf(v0, f0.x, acc.x); acc.y = fmaf(v0, f0.y, acc.y);
        acc.x = fmaf(v1, f1.x, acc.x); acc.y = fmaf(v1, f1.y, acc.y);
        acc.x = fmaf(v2, f2.x, acc.x); acc.y = fmaf(v2, f2.y, acc.y);
        acc.x = fmaf(v3, f3.x, acc.x); acc.y = fmaf(v3, f3.y, acc.y);
    }
    for (; e < end; ++e) {
        int2 p = __ldg(&g_edges[e]);
        float v = __int_as_float(p.y);
        float2 f = *reinterpret_cast<const float2*>(Y + (size_t)p.x * 64 + lane * 2);
        acc.x = fmaf(v, f.x, acc.x); acc.y = fmaf(v, f.y, acc.y);
    }

    // warp softmax over the 64-value row (2 per lane)
    float m = fmaxf(acc.x, acc.y);
#pragma unroll
    for (int o = 16; o; o >>= 1) m = fmaxf(m, __shfl_xor_sync(0xffffffffu, m, o));
    float e0 = __expf(acc.x - m);
    float e1 = __expf(acc.y - m);
    float ssum = e0 + e1;
#pragma unroll
    for (int o = 16; o; o >>= 1) ssum += __shfl_xor_sync(0xffffffffu, ssum, o);
    float inv = 1.f / ssum;
    *reinterpret_cast<float2*>(out + (size_t)d * 64 + lane * 2) =
        make_float2(e0 * inv, e1 * inv);
}

// ---------------------------------------------------------------------------
// Launch. Inputs: x, vals, W1, W2, src, dst. Output fp32 [N, 64].
// Order puts gemm128 in the ncu capture slot (#5).
// ---------------------------------------------------------------------------
extern "C" void kernel_launch(void* const* d_in, const int* in_sizes, int n_in,
                              void* d_out, int out_size)
{
    const float* x    = (const float*)d_in[0];
    const float* vals = (const float*)d_in[1];
    const float* W1   = (const float*)d_in[2];
    const float* W2   = (const float*)d_in[3];
    const int*   src  = (const int*)d_in[4];
    const int*   dst  = (const int*)d_in[5];
    float*       out  = (float*)d_out;

    const int M = in_sizes[0] / NF;   // 50000
    const int E = in_sizes[1];        // 800000

    float *y1, *s1, *y2;
    int* degp;
    cudaGetSymbolAddress((void**)&y1, g_y1);
    cudaGetSymbolAddress((void**)&s1, g_s1);
    cudaGetSymbolAddress((void**)&y2, g_y2);
    cudaGetSymbolAddress((void**)&degp, g_deg);

    const int nb = (M + SCAN_B - 1) / SCAN_B;           // 98
    const int gemmBlocks = (M + 127) / 128;

    cudaMemsetAsync(degp, 0, M * sizeof(int));                              // 1
    hist_kernel<<<(E + 255) / 256, 256>>>(dst, E);                          // 2
    scan1_kernel<<<nb, SCAN_B>>>(M);                                        // 3
    scan23_kernel<<<(M + 255) / 256, 256>>>(M, nb, E);                      // 4
    gemm_tc_kernel<128, false><<<gemmBlocks, 256>>>(x, W1, y1, M);          // 5 (ncu slot)
    permute_kernel<<<(E + 255) / 256, 256>>>(src, dst, vals, E);            // 6
    gather128_kernel<<<(M * 32 + 255) / 256, 256>>>(y1, s1, M);             // 7
    gemm_tc_kernel<64, true><<<gemmBlocks, 256>>>(s1, W2, y2, M);           // 8
    gather64_softmax_kernel<<<(M * 32 + 255) / 256, 256>>>(y2, out, M);     // 9
}

// round 11
// speedup vs baseline: 1.6162x; 1.0877x over previous
#include <cuda_runtime.h>
#include <cuda_fp16.h>
#include <cstdint>
#include <cstddef>

#define MAXN 50000
#define MAXE 800000
#define NF   128
#define NOUT 64
#define SCAN_B 512

// Scratch (no allocations allowed -> __device__ globals).
// y1/y2 held as fp16 (declared as uint2 for 8B alignment guarantees).
__device__ uint2 g_y1h[(size_t)MAXN * NF / 4];    // x @ W1^T            (half)
__device__ float g_s1[(size_t)MAXN * NF];         // gather-spmm(y1)     (fp32)
__device__ uint2 g_y2h[(size_t)MAXN * NOUT / 4];  // relu(s1) @ W2^T     (half)
__device__ int   g_deg[MAXN];                     // degree counts, then write-cursor
__device__ int   g_off[MAXN + 1];                 // CSR row offsets (by dst)
__device__ int   g_bsum[SCAN_B];                  // scan block sums
__device__ int2  g_edges[MAXE];                   // {src, __float_as_int(val)} by dst

// ---------------------------------------------------------------------------
// CSR build: histogram -> scan1 (per-block) -> scan23 (apply) -> permute
// ---------------------------------------------------------------------------
__global__ void hist_kernel(const int* __restrict__ dst, int E) {
    int i = blockIdx.x * blockDim.x + threadIdx.x;
    if (i < E) atomicAdd(&g_deg[__ldg(dst + i)], 1);
}

__global__ __launch_bounds__(SCAN_B) void scan1_kernel(int n) {
    __shared__ int sh[SCAN_B];
    int t = threadIdx.x;
    int i = blockIdx.x * SCAN_B + t;
    int v = (i < n) ? g_deg[i] : 0;
    sh[t] = v;
    __syncthreads();
#pragma unroll
    for (int o = 1; o < SCAN_B; o <<= 1) {
        int u = (t >= o) ? sh[t - o] : 0;
        __syncthreads();
        sh[t] += u;
        __syncthreads();
    }
    if (i <= n && i < MAXN + 1) g_off[i] = sh[t] - v;   // block-local exclusive
    if (t == SCAN_B - 1) g_bsum[blockIdx.x] = sh[t];
}

__global__ void scan23_kernel(int n, int nb, int E) {
    __shared__ int pref[256];            // nb <= 98
    int t = threadIdx.x;
    if (t == 0) {
        int run = 0;
        for (int b = 0; b < nb; ++b) { pref[b] = run; run += g_bsum[b]; }
    }
    __syncthreads();
    int i = blockIdx.x * blockDim.x + t;
    if (i < n) {
        int o = g_off[i] + pref[i >> 9];
        g_off[i] = o;
        g_deg[i] = o;                                   // reuse deg[] as write cursor
    }
    if (i == 0) g_off[n] = E;
}

__global__ void permute_kernel(const int* __restrict__ src, const int* __restrict__ dst,
                               const float* __restrict__ vals, int E) {
    int e = blockIdx.x * blockDim.x + threadIdx.x;
    if (e >= E) return;
    int pos = atomicAdd(&g_deg[__ldg(dst + e)], 1);
    g_edges[pos] = make_int2(__ldg(src + e), __float_as_int(__ldg(vals + e)));
}

// ---------------------------------------------------------------------------
// tf32 / mma / ldmatrix helpers
// ---------------------------------------------------------------------------
__device__ __forceinline__ uint32_t f2tf32(float x) {
    uint32_t r;
    asm("cvt.rna.tf32.f32 %0, %1;" : "=r"(r) : "f"(x));
    return r;
}

__device__ __forceinline__ void mma_tf32(float* d, const uint32_t* a, uint32_t b0, uint32_t b1) {
    asm volatile(
        "mma.sync.aligned.m16n8k8.row.col.f32.tf32.tf32.f32 "
        "{%0,%1,%2,%3}, {%4,%5,%6,%7}, {%8,%9}, {%0,%1,%2,%3};"
        : "+f"(d[0]), "+f"(d[1]), "+f"(d[2]), "+f"(d[3])
        : "r"(a[0]), "r"(a[1]), "r"(a[2]), "r"(a[3]), "r"(b0), "r"(b1));
}

__device__ __forceinline__ void ldm_x4(uint32_t* r, uint32_t saddr) {
    asm volatile("ldmatrix.sync.aligned.m8n8.x4.shared.b16 {%0,%1,%2,%3}, [%4];"
                 : "=r"(r[0]), "=r"(r[1]), "=r"(r[2]), "=r"(r[3]) : "r"(saddr));
}

// ---------------------------------------------------------------------------
// C[M, NCOLS] (fp16) = act(A fp32)[M, 128] @ W[NCOLS, 128]^T via 3xTF32 MMA.
// ldmatrix fragment loads + hi/lo tf32 split; epilogue stores half2.
// ---------------------------------------------------------------------------
template <int NCOLS, bool RELU_IN>
__global__ __launch_bounds__(256) void gemm_tc_kernel(
    const float* __restrict__ A, const float* __restrict__ W,
    __half* __restrict__ C, int M)
{
    constexpr int BK   = 16;
    constexpr int STRD = 20;
    constexpr int NT   = NCOLS / 16;

    __shared__ uint32_t As_hi[128 * STRD];
    __shared__ uint32_t As_lo[128 * STRD];
    __shared__ uint32_t Bs_hi[NCOLS * STRD];
    __shared__ uint32_t Bs_lo[NCOLS * STRD];

    const int tid  = threadIdx.x;
    const int wid  = tid >> 5;
    const int lane = tid & 31;
    const int g    = lane >> 2;
    const int t    = lane & 3;
    const int warp_m = wid >> 1;
    const int warp_n = wid & 1;
    const int blockRow = blockIdx.x * 128;

    float acc[2][NT][4];
#pragma unroll
    for (int mt = 0; mt < 2; ++mt)
#pragma unroll
        for (int nt = 0; nt < NT; ++nt)
#pragma unroll
            for (int i = 0; i < 4; ++i) acc[mt][nt][i] = 0.f;

    const uint32_t sAhi = (uint32_t)__cvta_generic_to_shared(As_hi);
    const uint32_t sAlo = (uint32_t)__cvta_generic_to_shared(As_lo);
    const uint32_t sBhi = (uint32_t)__cvta_generic_to_shared(Bs_hi);
    const uint32_t sBlo = (uint32_t)__cvta_generic_to_shared(Bs_lo);

    const int  arow  = tid >> 1;
    const int  akoff = (tid & 1) * 8;
    const int  gArow = blockRow + arow;
    const bool aok   = (gArow < M);

    const int a_lr = lane & 15;
    const int a_lk = (lane >> 4) * 4;
    const int b_lr = (lane & 7) + ((lane >> 4) << 3);
    const int b_lk = ((lane >> 3) & 1) * 4;

    for (int k0 = 0; k0 < 128; k0 += BK) {
        {
            float4 v0 = make_float4(0.f, 0.f, 0.f, 0.f);
            float4 v1 = make_float4(0.f, 0.f, 0.f, 0.f);
            if (aok) {
                v0 = *reinterpret_cast<const float4*>(A + (size_t)gArow * 128 + k0 + akoff);
                v1 = *reinterpret_cast<const float4*>(A + (size_t)gArow * 128 + k0 + akoff + 4);
            }
            float vv[8] = {v0.x, v0.y, v0.z, v0.w, v1.x, v1.y, v1.z, v1.w};
            uint32_t hi[8], lo[8];
#pragma unroll
            for (int j = 0; j < 8; ++j) {
                float f = RELU_IN ? fmaxf(vv[j], 0.f) : vv[j];
                hi[j] = f2tf32(f);
                lo[j] = f2tf32(f - __uint_as_float(hi[j]));
            }
            uint32_t* ph = &As_hi[arow * STRD + akoff];
            uint32_t* pl = &As_lo[arow * STRD + akoff];
            *reinterpret_cast<uint4*>(ph)     = make_uint4(hi[0], hi[1], hi[2], hi[3]);
            *reinterpret_cast<uint4*>(ph + 4) = make_uint4(hi[4], hi[5], hi[6], hi[7]);
            *reinterpret_cast<uint4*>(pl)     = make_uint4(lo[0], lo[1], lo[2], lo[3]);
            *reinterpret_cast<uint4*>(pl + 4) = make_uint4(lo[4], lo[5], lo[6], lo[7]);
        }
        if (NCOLS == 128) {
            int brow  = tid >> 1;
            int bkoff = (tid & 1) * 8;
            float4 v0 = *reinterpret_cast<const float4*>(W + (size_t)brow * 128 + k0 + bkoff);
            float4 v1 = *reinterpret_cast<const float4*>(W + (size_t)brow * 128 + k0 + bkoff + 4);
            float vv[8] = {v0.x, v0.y, v0.z, v0.w, v1.x, v1.y, v1.z, v1.w};
            uint32_t hi[8], lo[8];
#pragma unroll
            for (int j = 0; j < 8; ++j) {
                hi[j] = f2tf32(vv[j]);
                lo[j] = f2tf32(vv[j] - __uint_as_float(hi[j]));
            }
            uint32_t* ph = &Bs_hi[brow * STRD + bkoff];
            uint32_t* pl = &Bs_lo[brow * STRD + bkoff];
            *reinterpret_cast<uint4*>(ph)     = make_uint4(hi[0], hi[1], hi[2], hi[3]);
            *reinterpret_cast<uint4*>(ph + 4) = make_uint4(hi[4], hi[5], hi[6], hi[7]);
            *reinterpret_cast<uint4*>(pl)     = make_uint4(lo[0], lo[1], lo[2], lo[3]);
            *reinterpret_cast<uint4*>(pl + 4) = make_uint4(lo[4], lo[5], lo[6], lo[7]);
        } else {
            int brow  = tid >> 2;
            int bkoff = (tid & 3) * 4;
            float4 v = *reinterpret_cast<const float4*>(W + (size_t)brow * 128 + k0 + bkoff);
            float vv[4] = {v.x, v.y, v.z, v.w};
            uint32_t hi[4], lo[4];
#pragma unroll
            for (int j = 0; j < 4; ++j) {
                hi[j] = f2tf32(vv[j]);
                lo[j] = f2tf32(vv[j] - __uint_as_float(hi[j]));
            }
            *reinterpret_cast<uint4*>(&Bs_hi[brow * STRD + bkoff]) = make_uint4(hi[0], hi[1], hi[2], hi[3]);
            *reinterpret_cast<uint4*>(&Bs_lo[brow * STRD + bkoff]) = make_uint4(lo[0], lo[1], lo[2], lo[3]);
        }
        __syncthreads();

#pragma unroll
        for (int ks = 0; ks < 2; ++ks) {
            const int kb = ks * 8;
            uint32_t ah[2][4], al[2][4];
#pragma unroll
            for (int mt = 0; mt < 2; ++mt) {
                int mrow = warp_m * 32 + mt * 16 + a_lr;
                uint32_t off = (uint32_t)(mrow * STRD + kb + a_lk) * 4u;
                ldm_x4(ah[mt], sAhi + off);
                ldm_x4(al[mt], sAlo + off);
            }
#pragma unroll
            for (int ntp = 0; ntp < NT / 2; ++ntp) {
                int nbase = warp_n * (NCOLS / 2) + ntp * 16;
                uint32_t off = (uint32_t)((nbase + b_lr) * STRD + kb + b_lk) * 4u;
                uint32_t bh[4], bl[4];
                ldm_x4(bh, sBhi + off);
                ldm_x4(bl, sBlo + off);
#pragma unroll
                for (int mt = 0; mt < 2; ++mt) {
                    mma_tf32(acc[mt][2 * ntp],     ah[mt], bh[0], bh[1]);
                    mma_tf32(acc[mt][2 * ntp],     ah[mt], bl[0], bl[1]);
                    mma_tf32(acc[mt][2 * ntp],     al[mt], bh[0], bh[1]);
                    mma_tf32(acc[mt][2 * ntp + 1], ah[mt], bh[2], bh[3]);
                    mma_tf32(acc[mt][2 * ntp + 1], ah[mt], bl[2], bl[3]);
                    mma_tf32(acc[mt][2 * ntp + 1], al[mt], bh[2], bh[3]);
                }
            }
        }
        __syncthreads();
    }

    // ---- store C as half2 pairs (cols 2t, 2t+1 are adjacent) ----
#pragma unroll
    for (int mt = 0; mt < 2; ++mt) {
#pragma unroll
        for (int half = 0; half < 2; ++half) {
            int row = blockRow + warp_m * 32 + mt * 16 + half * 8 + g;
            if (row < M) {
#pragma unroll
                for (int nt = 0; nt < NT; ++nt) {
                    int col = warp_n * (NCOLS / 2) + nt * 8 + 2 * t;
                    __half2 h = __float22half2_rn(
                        make_float2(acc[mt][nt][half * 2], acc[mt][nt][half * 2 + 1]));
                    *reinterpret_cast<__half2*>(C + (size_t)row * NCOLS + col) = h;
                }
            }
        }
    }
}

// ---------------------------------------------------------------------------
// Gather SPMM, 128-wide fp16 input: warp/node, 4 halfs/lane, fp32 accumulate.
// ---------------------------------------------------------------------------
__global__ __launch_bounds__(256) void gather128_kernel(
    const __half* __restrict__ Y, float* __restrict__ S, int n)
{
    int gid  = blockIdx.x * blockDim.x + threadIdx.x;
    int d    = gid >> 5;
    int lane = threadIdx.x & 31;
    if (d >= n) return;
    int beg = g_off[d], end = g_off[d + 1];

    float4 acc = make_float4(0.f, 0.f, 0.f, 0.f);
    int e = beg;
    for (; e + 3 < end; e += 4) {
        int2 p0 = __ldg(&g_edges[e]);
        int2 p1 = __ldg(&g_edges[e + 1]);
        int2 p2 = __ldg(&g_edges[e + 2]);
        int2 p3 = __ldg(&g_edges[e + 3]);
        uint2 u0 = __ldg(reinterpret_cast<const uint2*>(Y + (size_t)p0.x * 128) + lane);
        uint2 u1 = __ldg(reinterpret_cast<const uint2*>(Y + (size_t)p1.x * 128) + lane);
        uint2 u2 = __ldg(reinterpret_cast<const uint2*>(Y + (size_t)p2.x * 128) + lane);
        uint2 u3 = __ldg(reinterpret_cast<const uint2*>(Y + (size_t)p3.x * 128) + lane);
        float v0 = __int_as_float(p0.y), v1 = __int_as_float(p1.y);
        float v2 = __int_as_float(p2.y), v3 = __int_as_float(p3.y);
        float2 a0 = __half22float2(*reinterpret_cast<__half2*>(&u0.x));
        float2 b0 = __half22float2(*reinterpret_cast<__half2*>(&u0.y));
        float2 a1 = __half22float2(*reinterpret_cast<__half2*>(&u1.x));
        float2 b1 = __half22float2(*reinterpret_cast<__half2*>(&u1.y));
        float2 a2 = __half22float2(*reinterpret_cast<__half2*>(&u2.x));
        float2 b2 = __half22float2(*reinterpret_cast<__half2*>(&u2.y));
        float2 a3 = __half22float2(*reinterpret_cast<__half2*>(&u3.x));
        float2 b3 = __half22float2(*reinterpret_cast<__half2*>(&u3.y));
        acc.x = fmaf(v0, a0.x, acc.x); acc.y = fmaf(v0, a0.y, acc.y);
        acc.z = fmaf(v0, b0.x, acc.z); acc.w = fmaf(v0, b0.y, acc.w);
        acc.x = fmaf(v1, a1.x, acc.x); acc.y = fmaf(v1, a1.y, acc.y);
        acc.z = fmaf(v1, b1.x, acc.z); acc.w = fmaf(v1, b1.y, acc.w);
        acc.x = fmaf(v2, a2.x, acc.x); acc.y = fmaf(v2, a2.y, acc.y);
        acc.z = fmaf(v2, b2.x, acc.z); acc.w = fmaf(v2, b2.y, acc.w);
        acc.x = fmaf(v3, a3.x, acc.x); acc.y = fmaf(v3, a3.y, acc.y);
        acc.z = fmaf(v3, b3.x, acc.z); acc.w = fmaf(v3, b3.y, acc.w);
    }
    for (; e < end; ++e) {
        int2 p = __ldg(&g_edges[e]);
        float v = __int_as_float(p.y);
        uint2 u = __ldg(reinterpret_cast<const uint2*>(Y + (size_t)p.x * 128) + lane);
        float2 a = __half22float2(*reinterpret_cast<__half2*>(&u.x));
        float2 b = __half22float2(*reinterpret_cast<__half2*>(&u.y));
        acc.x = fmaf(v, a.x, acc.x); acc.y = fmaf(v, a.y, acc.y);
        acc.z = fmaf(v, b.x, acc.z); acc.w = fmaf(v, b.y, acc.w);
    }
    // lane holds cols [4*lane, 4*lane+3]
    *reinterpret_cast<float4*>(S + (size_t)d * 128 + lane * 4) = acc;
}

// ---------------------------------------------------------------------------
// Gather SPMM, 64-wide fp16 input, fused row softmax: warp/node, 2 halfs/lane.
// ---------------------------------------------------------------------------
__global__ __launch_bounds__(256) void gather64_softmax_kernel(
    const __half* __restrict__ Y, float* __restrict__ out, int n)
{
    int gid  = blockIdx.x * blockDim.x + threadIdx.x;
    int d    = gid >> 5;
    int lane = threadIdx.x & 31;
    if (d >= n) return;
    int beg = g_off[d], end = g_off[d + 1];

    float2 acc = make_float2(0.f, 0.f);
    int e = beg;
    for (; e + 3 < end; e += 4) {
        int2 p0 = __ldg(&g_edges[e]);
        int2 p1 = __ldg(&g_edges[e + 1]);
        int2 p2 = __ldg(&g_edges[e + 2]);
        int2 p3 = __ldg(&g_edges[e + 3]);
        uint32_t u0 = __ldg(reinterpret_cast<const uint32_t*>(Y + (size_t)p0.x * 64) + lane);
        uint32_t u1 = __ldg(reinterpret_cast<const uint32_t*>(Y + (size_t)p1.x * 64) + lane);
        uint32_t u2 = __ldg(reinterpret_cast<const uint32_t*>(Y + (size_t)p2.x * 64) + lane);
        uint32_t u3 = __ldg(reinterpret_cast<const uint32_t*>(Y + (size_t)p3.x * 64) + lane);
        float v0 = __int_as_float(p0.y), v1 = __int_as_float(p1.y);
        float v2 = __int_as_float(p2.y), v3 = __int_as_float(p3.y);
        float2 f0 = __half22float2(*reinterpret_cast<__half2*>(&u0));
        float2 f1 = __half22float2(*reinterpret_cast<__half2*>(&u1));
        float2 f2 = __half22float2(*reinterpret_cast<__half2*>(&u2));
        float2 f3 = __half22float2(*reinterpret_cast<__half2*>(&u3));
        acc.x = fmaf(v0, f0.x, acc.x); acc.y = fmaf(v0, f0.y, acc.y);
        acc.x = fmaf(v1, f1.x, acc.x); acc.y = fmaf(v1, f1.y, acc.y);
        acc.x = fmaf(v2, f2.x, acc.x); acc.y = fmaf(v2, f2.y, acc.y);
        acc.x = fmaf(v3, f3.x, acc.x); acc.y = fmaf(v3, f3.y, acc.y);
    }
    for (; e < end; ++e) {
        int2 p = __ldg(&g_edges[e]);
        float v = __int_as_float(p.y);
        uint32_t u = __ldg(reinterpret_cast<const uint32_t*>(Y + (size_t)p.x * 64) + lane);
        float2 f = __half22float2(*reinterpret_cast<__half2*>(&u));
        acc.x = fmaf(v, f.x, acc.x); acc.y = fmaf(v, f.y, acc.y);
    }

    // warp softmax over the 64-value row (2 per lane)
    float m = fmaxf(acc.x, acc.y);
#pragma unroll
    for (int o = 16; o; o >>= 1) m = fmaxf(m, __shfl_xor_sync(0xffffffffu, m, o));
    float e0 = __expf(acc.x - m);
    float e1 = __expf(acc.y - m);
    float ssum = e0 + e1;
#pragma unroll
    for (int o = 16; o; o >>= 1) ssum += __shfl_xor_sync(0xffffffffu, ssum, o);
    float inv = 1.f / ssum;
    *reinterpret_cast<float2*>(out + (size_t)d * 64 + lane * 2) =
        make_float2(e0 * inv, e1 * inv);
}

// ---------------------------------------------------------------------------
// Launch. Inputs: x, vals, W1, W2, src, dst. Output fp32 [N, 64].
// Slot 5 = gemm128 (ncu capture).
// ---------------------------------------------------------------------------
extern "C" void kernel_launch(void* const* d_in, const int* in_sizes, int n_in,
                              void* d_out, int out_size)
{
    const float* x    = (const float*)d_in[0];
    const float* vals = (const float*)d_in[1];
    const float* W1   = (const float*)d_in[2];
    const float* W2   = (const float*)d_in[3];
    const int*   src  = (const int*)d_in[4];
    const int*   dst  = (const int*)d_in[5];
    float*       out  = (float*)d_out;

    const int M = in_sizes[0] / NF;   // 50000
    const int E = in_sizes[1];        // 800000

    __half *y1h, *y2h;
    float* s1;
    int* degp;
    cudaGetSymbolAddress((void**)&y1h, g_y1h);
    cudaGetSymbolAddress((void**)&s1, g_s1);
    cudaGetSymbolAddress((void**)&y2h, g_y2h);
    cudaGetSymbolAddress((void**)&degp, g_deg);

    const int nb = (M + SCAN_B - 1) / SCAN_B;           // 98
    const int gemmBlocks = (M + 127) / 128;

    cudaMemsetAsync(degp, 0, M * sizeof(int));                              // 1
    hist_kernel<<<(E + 255) / 256, 256>>>(dst, E);                          // 2
    scan1_kernel<<<nb, SCAN_B>>>(M);                                        // 3
    scan23_kernel<<<(M + 255) / 256, 256>>>(M, nb, E);                      // 4
    gemm_tc_kernel<128, false><<<gemmBlocks, 256>>>(x, W1, y1h, M);         // 5 (ncu slot)
    permute_kernel<<<(E + 255) / 256, 256>>>(src, dst, vals, E);            // 6
    gather128_kernel<<<(M * 32 + 255) / 256, 256>>>(y1h, s1, M);            // 7
    gemm_tc_kernel<64, true><<<gemmBlocks, 256>>>(s1, W2, y2h, M);          // 8
    gather64_softmax_kernel<<<(M * 32 + 255) / 256, 256>>>(y2h, out, M);    // 9
}

// round 12
// speedup vs baseline: 1.9094x; 1.1814x over previous
#include <cuda_runtime.h>
#include <cuda_fp16.h>
#include <cstdint>
#include <cstddef>

#define MAXN 50000
#define MAXE 800000
#define NF   128
#define NOUT 64
#define SCAN_B 512

// Scratch (no allocations allowed -> __device__ globals).
__device__ uint2 g_y1h[(size_t)MAXN * NF / 4];    // x @ W1^T            (half)
__device__ float g_s1[(size_t)MAXN * NF];         // gather-spmm(y1)     (fp32)
__device__ uint2 g_y2h[(size_t)MAXN * NOUT / 4];  // relu(s1) @ W2^T     (half)
__device__ int   g_deg[MAXN];                     // degree counts, then write-cursor
__device__ int   g_off[MAXN + 1];                 // CSR row offsets (by dst)
__device__ int   g_bsum[SCAN_B];                  // scan block sums
__device__ int2  g_edges[MAXE];                   // {src, __float_as_int(val)} by dst

// ---------------------------------------------------------------------------
// CSR build: histogram -> scan1 (per-block) -> scan23 (apply) -> permute
// ---------------------------------------------------------------------------
__global__ void hist_kernel(const int* __restrict__ dst, int E) {
    int i = blockIdx.x * blockDim.x + threadIdx.x;
    if (i < E) atomicAdd(&g_deg[__ldg(dst + i)], 1);
}

__global__ __launch_bounds__(SCAN_B) void scan1_kernel(int n) {
    __shared__ int sh[SCAN_B];
    int t = threadIdx.x;
    int i = blockIdx.x * SCAN_B + t;
    int v = (i < n) ? g_deg[i] : 0;
    sh[t] = v;
    __syncthreads();
#pragma unroll
    for (int o = 1; o < SCAN_B; o <<= 1) {
        int u = (t >= o) ? sh[t - o] : 0;
        __syncthreads();
        sh[t] += u;
        __syncthreads();
    }
    if (i <= n && i < MAXN + 1) g_off[i] = sh[t] - v;
    if (t == SCAN_B - 1) g_bsum[blockIdx.x] = sh[t];
}

__global__ void scan23_kernel(int n, int nb, int E) {
    __shared__ int pref[256];
    int t = threadIdx.x;
    if (t == 0) {
        int run = 0;
        for (int b = 0; b < nb; ++b) { pref[b] = run; run += g_bsum[b]; }
    }
    __syncthreads();
    int i = blockIdx.x * blockDim.x + t;
    if (i < n) {
        int o = g_off[i] + pref[i >> 9];
        g_off[i] = o;
        g_deg[i] = o;
    }
    if (i == 0) g_off[n] = E;
}

__global__ void permute_kernel(const int* __restrict__ src, const int* __restrict__ dst,
                               const float* __restrict__ vals, int E) {
    int e = blockIdx.x * blockDim.x + threadIdx.x;
    if (e >= E) return;
    int pos = atomicAdd(&g_deg[__ldg(dst + e)], 1);
    g_edges[pos] = make_int2(__ldg(src + e), __float_as_int(__ldg(vals + e)));
}

// ---------------------------------------------------------------------------
// bf16 / mma / ldmatrix helpers
// ---------------------------------------------------------------------------
__device__ __forceinline__ uint32_t bf16x2_rn(float f0, float f1) {
    // result: low half = bf16(f0), high half = bf16(f1)
    uint32_t r;
    asm("cvt.rn.bf16x2.f32 %0, %1, %2;" : "=r"(r) : "f"(f1), "f"(f0));
    return r;
}

// Convert 8 consecutive floats into 4 hi bf16x2 words + 4 lo (residual) words.
template <bool RELU>
__device__ __forceinline__ void cvt8_bf(const float* v, uint32_t* hw, uint32_t* lw) {
#pragma unroll
    for (int p = 0; p < 4; ++p) {
        float f0 = v[2 * p], f1 = v[2 * p + 1];
        if (RELU) { f0 = fmaxf(f0, 0.f); f1 = fmaxf(f1, 0.f); }
        uint32_t h = bf16x2_rn(f0, f1);
        float h0 = __uint_as_float(h << 16);
        float h1 = __uint_as_float(h & 0xFFFF0000u);
        uint32_t l = bf16x2_rn(f0 - h0, f1 - h1);
        hw[p] = h; lw[p] = l;
    }
}

__device__ __forceinline__ void mma_bf16(float* d, const uint32_t* a, uint32_t b0, uint32_t b1) {
    asm volatile(
        "mma.sync.aligned.m16n8k16.row.col.f32.bf16.bf16.f32 "
        "{%0,%1,%2,%3}, {%4,%5,%6,%7}, {%8,%9}, {%0,%1,%2,%3};"
        : "+f"(d[0]), "+f"(d[1]), "+f"(d[2]), "+f"(d[3])
        : "r"(a[0]), "r"(a[1]), "r"(a[2]), "r"(a[3]), "r"(b0), "r"(b1));
}

__device__ __forceinline__ void ldm_x4(uint32_t* r, uint32_t saddr) {
    asm volatile("ldmatrix.sync.aligned.m8n8.x4.shared.b16 {%0,%1,%2,%3}, [%4];"
                 : "=r"(r[0]), "=r"(r[1]), "=r"(r[2]), "=r"(r[3]) : "r"(saddr));
}

// ---------------------------------------------------------------------------
// C[M, NCOLS] (fp16) = act(A fp32)[M, 128] @ W[NCOLS, 128]^T via 3xBF16 MMA
// (hi/lo split: ah*bh + ah*bl + al*bh; dropped term ~2^-16).
// BK=32 staged as packed bf16x2, STRD=20 words (conflict-free ldmatrix phases).
// m16n8k16 MMA: half the tensor instructions of the tf32-k8 version.
// ---------------------------------------------------------------------------
template <int NCOLS, bool RELU_IN>
__global__ __launch_bounds__(256) void gemm_tc_kernel(
    const float* __restrict__ A, const float* __restrict__ W,
    __half* __restrict__ C, int M)
{
    constexpr int BK   = 32;             // k floats per staged tile
    constexpr int STRD = 20;             // words per staged row (16 data + 4 pad)
    constexpr int NT   = NCOLS / 16;     // n8-tiles per warp (8 or 4)

    __shared__ __align__(16) uint32_t As_hi[128 * STRD];
    __shared__ __align__(16) uint32_t As_lo[128 * STRD];
    __shared__ __align__(16) uint32_t Bs_hi[NCOLS * STRD];
    __shared__ __align__(16) uint32_t Bs_lo[NCOLS * STRD];

    const int tid  = threadIdx.x;
    const int wid  = tid >> 5;
    const int lane = tid & 31;
    const int g    = lane >> 2;
    const int t    = lane & 3;
    const int warp_m = wid >> 1;
    const int warp_n = wid & 1;
    const int blockRow = blockIdx.x * 128;

    float acc[2][NT][4];
#pragma unroll
    for (int mt = 0; mt < 2; ++mt)
#pragma unroll
        for (int nt = 0; nt < NT; ++nt)
#pragma unroll
            for (int i = 0; i < 4; ++i) acc[mt][nt][i] = 0.f;

    const uint32_t sAhi = (uint32_t)__cvta_generic_to_shared(As_hi);
    const uint32_t sAlo = (uint32_t)__cvta_generic_to_shared(As_lo);
    const uint32_t sBhi = (uint32_t)__cvta_generic_to_shared(Bs_hi);
    const uint32_t sBlo = (uint32_t)__cvta_generic_to_shared(Bs_lo);

    // A staging: 2 threads/row, 16 consecutive k floats each.
    const int  arow  = tid >> 1;
    const int  akoff = (tid & 1) * 16;
    const int  gArow = blockRow + arow;
    const bool aok   = (gArow < M);

    // ldmatrix lane addressing (byte offsets within a k32 tile):
    // A m16k16 frag: lanes0-15 -> m-rows, k-lo 16B; lanes16-31 -> k-hi 16B.
    const int a_lr = lane & 15;
    const int a_kb = (lane >> 4) * 16;
    // B n16k16 frag: lanes0-7 n-lo/k-lo, 8-15 n-lo/k-hi, 16-23 n-hi/k-lo, 24-31 n-hi/k-hi.
    const int b_lr = (lane & 7) + ((lane >> 4) << 3);
    const int b_kb = ((lane >> 3) & 1) * 16;

    for (int k0 = 0; k0 < 128; k0 += BK) {
        // ---- stage A rows [m][k] as bf16x2 hi/lo ----
        {
            float v[16];
#pragma unroll
            for (int j = 0; j < 16; ++j) v[j] = 0.f;
            if (aok) {
                const float* ap = A + (size_t)gArow * 128 + k0 + akoff;
                *reinterpret_cast<float4*>(v)      = *reinterpret_cast<const float4*>(ap);
                *reinterpret_cast<float4*>(v + 4)  = *reinterpret_cast<const float4*>(ap + 4);
                *reinterpret_cast<float4*>(v + 8)  = *reinterpret_cast<const float4*>(ap + 8);
                *reinterpret_cast<float4*>(v + 12) = *reinterpret_cast<const float4*>(ap + 12);
            }
            uint32_t hw[8], lw[8];
            cvt8_bf<RELU_IN>(v, hw, lw);
            cvt8_bf<RELU_IN>(v + 8, hw + 4, lw + 4);
            int wo = arow * STRD + (akoff >> 1);
            *reinterpret_cast<uint4*>(&As_hi[wo])     = make_uint4(hw[0], hw[1], hw[2], hw[3]);
            *reinterpret_cast<uint4*>(&As_hi[wo + 4]) = make_uint4(hw[4], hw[5], hw[6], hw[7]);
            *reinterpret_cast<uint4*>(&As_lo[wo])     = make_uint4(lw[0], lw[1], lw[2], lw[3]);
            *reinterpret_cast<uint4*>(&As_lo[wo + 4]) = make_uint4(lw[4], lw[5], lw[6], lw[7]);
        }
        // ---- stage W rows [n][k] as bf16x2 hi/lo ----
        if (NCOLS == 128) {
            int brow  = tid >> 1;
            int bkoff = (tid & 1) * 16;
            float v[16];
            const float* wp = W + (size_t)brow * 128 + k0 + bkoff;
            *reinterpret_cast<float4*>(v)      = *reinterpret_cast<const float4*>(wp);
            *reinterpret_cast<float4*>(v + 4)  = *reinterpret_cast<const float4*>(wp + 4);
            *reinterpret_cast<float4*>(v + 8)  = *reinterpret_cast<const float4*>(wp + 8);
            *reinterpret_cast<float4*>(v + 12) = *reinterpret_cast<const float4*>(wp + 12);
            uint32_t hw[8], lw[8];
            cvt8_bf<false>(v, hw, lw);
            cvt8_bf<false>(v + 8, hw + 4, lw + 4);
            int wo = brow * STRD + (bkoff >> 1);
            *reinterpret_cast<uint4*>(&Bs_hi[wo])     = make_uint4(hw[0], hw[1], hw[2], hw[3]);
            *reinterpret_cast<uint4*>(&Bs_hi[wo + 4]) = make_uint4(hw[4], hw[5], hw[6], hw[7]);
            *reinterpret_cast<uint4*>(&Bs_lo[wo])     = make_uint4(lw[0], lw[1], lw[2], lw[3]);
            *reinterpret_cast<uint4*>(&Bs_lo[wo + 4]) = make_uint4(lw[4], lw[5], lw[6], lw[7]);
        } else {
            int brow  = tid >> 2;                // 0..63
            int bkoff = (tid & 3) * 8;
            float v[8];
            const float* wp = W + (size_t)brow * 128 + k0 + bkoff;
            *reinterpret_cast<float4*>(v)     = *reinterpret_cast<const float4*>(wp);
            *reinterpret_cast<float4*>(v + 4) = *reinterpret_cast<const float4*>(wp + 4);
            uint32_t hw[4], lw[4];
            cvt8_bf<false>(v, hw, lw);
            int wo = brow * STRD + (bkoff >> 1);
            *reinterpret_cast<uint4*>(&Bs_hi[wo]) = make_uint4(hw[0], hw[1], hw[2], hw[3]);
            *reinterpret_cast<uint4*>(&Bs_lo[wo]) = make_uint4(lw[0], lw[1], lw[2], lw[3]);
        }
        __syncthreads();

        // ---- 2 mma k16-steps per staged k32 tile ----
#pragma unroll
        for (int ks = 0; ks < 2; ++ks) {
            const int kbyte = ks * 32;
            uint32_t ah[2][4], al[2][4];
#pragma unroll
            for (int mt = 0; mt < 2; ++mt) {
                uint32_t off = (uint32_t)((warp_m * 32 + mt * 16 + a_lr) * STRD) * 4u + kbyte + a_kb;
                ldm_x4(ah[mt], sAhi + off);
                ldm_x4(al[mt], sAlo + off);
            }
#pragma unroll
            for (int ntp = 0; ntp < NT / 2; ++ntp) {
                int nbase = warp_n * (NCOLS / 2) + ntp * 16;
                uint32_t off = (uint32_t)((nbase + b_lr) * STRD) * 4u + kbyte + b_kb;
                uint32_t bh[4], bl[4];
                ldm_x4(bh, sBhi + off);
                ldm_x4(bl, sBlo + off);
#pragma unroll
                for (int mt = 0; mt < 2; ++mt) {
                    mma_bf16(acc[mt][2 * ntp],     ah[mt], bh[0], bh[1]);
                    mma_bf16(acc[mt][2 * ntp],     ah[mt], bl[0], bl[1]);
                    mma_bf16(acc[mt][2 * ntp],     al[mt], bh[0], bh[1]);
                    mma_bf16(acc[mt][2 * ntp + 1], ah[mt], bh[2], bh[3]);
                    mma_bf16(acc[mt][2 * ntp + 1], ah[mt], bl[2], bl[3]);
                    mma_bf16(acc[mt][2 * ntp + 1], al[mt], bh[2], bh[3]);
                }
            }
        }
        __syncthreads();
    }

    // ---- store C as half2 pairs ----
#pragma unroll
    for (int mt = 0; mt < 2; ++mt) {
#pragma unroll
        for (int half = 0; half < 2; ++half) {
            int row = blockRow + warp_m * 32 + mt * 16 + half * 8 + g;
            if (row < M) {
#pragma unroll
                for (int nt = 0; nt < NT; ++nt) {
                    int col = warp_n * (NCOLS / 2) + nt * 8 + 2 * t;
                    __half2 h = __float22half2_rn(
                        make_float2(acc[mt][nt][half * 2], acc[mt][nt][half * 2 + 1]));
                    *reinterpret_cast<__half2*>(C + (size_t)row * NCOLS + col) = h;
                }
            }
        }
    }
}

// ---------------------------------------------------------------------------
// Gather SPMM, 128-wide fp16 input: warp/node, 4 halfs/lane, fp32 accumulate.
// ---------------------------------------------------------------------------
__global__ __launch_bounds__(256) void gather128_kernel(
    const __half* __restrict__ Y, float* __restrict__ S, int n)
{
    int gid  = blockIdx.x * blockDim.x + threadIdx.x;
    int d    = gid >> 5;
    int lane = threadIdx.x & 31;
    if (d >= n) return;
    int beg = g_off[d], end = g_off[d + 1];

    float4 acc = make_float4(0.f, 0.f, 0.f, 0.f);
    int e = beg;
    for (; e + 3 < end; e += 4) {
        int2 p0 = __ldg(&g_edges[e]);
        int2 p1 = __ldg(&g_edges[e + 1]);
        int2 p2 = __ldg(&g_edges[e + 2]);
        int2 p3 = __ldg(&g_edges[e + 3]);
        uint2 u0 = __ldg(reinterpret_cast<const uint2*>(Y + (size_t)p0.x * 128) + lane);
        uint2 u1 = __ldg(reinterpret_cast<const uint2*>(Y + (size_t)p1.x * 128) + lane);
        uint2 u2 = __ldg(reinterpret_cast<const uint2*>(Y + (size_t)p2.x * 128) + lane);
        uint2 u3 = __ldg(reinterpret_cast<const uint2*>(Y + (size_t)p3.x * 128) + lane);
        float v0 = __int_as_float(p0.y), v1 = __int_as_float(p1.y);
        float v2 = __int_as_float(p2.y), v3 = __int_as_float(p3.y);
        float2 a0 = __half22float2(*reinterpret_cast<__half2*>(&u0.x));
        float2 b0 = __half22float2(*reinterpret_cast<__half2*>(&u0.y));
        float2 a1 = __half22float2(*reinterpret_cast<__half2*>(&u1.x));
        float2 b1 = __half22float2(*reinterpret_cast<__half2*>(&u1.y));
        float2 a2 = __half22float2(*reinterpret_cast<__half2*>(&u2.x));
        float2 b2 = __half22float2(*reinterpret_cast<__half2*>(&u2.y));
        float2 a3 = __half22float2(*reinterpret_cast<__half2*>(&u3.x));
        float2 b3 = __half22float2(*reinterpret_cast<__half2*>(&u3.y));
        acc.x = fmaf(v0, a0.x, acc.x); acc.y = fmaf(v0, a0.y, acc.y);
        acc.z = fmaf(v0, b0.x, acc.z); acc.w = fmaf(v0, b0.y, acc.w);
        acc.x = fmaf(v1, a1.x, acc.x); acc.y = fmaf(v1, a1.y, acc.y);
        acc.z = fmaf(v1, b1.x, acc.z); acc.w = fmaf(v1, b1.y, acc.w);
        acc.x = fmaf(v2, a2.x, acc.x); acc.y = fmaf(v2, a2.y, acc.y);
        acc.z = fmaf(v2, b2.x, acc.z); acc.w = fmaf(v2, b2.y, acc.w);
        acc.x = fmaf(v3, a3.x, acc.x); acc.y = fmaf(v3, a3.y, acc.y);
        acc.z = fmaf(v3, b3.x, acc.z); acc.w = fmaf(v3, b3.y, acc.w);
    }
    for (; e < end; ++e) {
        int2 p = __ldg(&g_edges[e]);
        float v = __int_as_float(p.y);
        uint2 u = __ldg(reinterpret_cast<const uint2*>(Y + (size_t)p.x * 128) + lane);
        float2 a = __half22float2(*reinterpret_cast<__half2*>(&u.x));
        float2 b = __half22float2(*reinterpret_cast<__half2*>(&u.y));
        acc.x = fmaf(v, a.x, acc.x); acc.y = fmaf(v, a.y, acc.y);
        acc.z = fmaf(v, b.x, acc.z); acc.w = fmaf(v, b.y, acc.w);
    }
    *reinterpret_cast<float4*>(S + (size_t)d * 128 + lane * 4) = acc;
}

// ---------------------------------------------------------------------------
// Gather SPMM, 64-wide fp16 input, fused row softmax: warp/node, 2 halfs/lane.
// ---------------------------------------------------------------------------
__global__ __launch_bounds__(256) void gather64_softmax_kernel(
    const __half* __restrict__ Y, float* __restrict__ out, int n)
{
    int gid  = blockIdx.x * blockDim.x + threadIdx.x;
    int d    = gid >> 5;
    int lane = threadIdx.x & 31;
    if (d >= n) return;
    int beg = g_off[d], end = g_off[d + 1];

    float2 acc = make_float2(0.f, 0.f);
    int e = beg;
    for (; e + 3 < end; e += 4) {
        int2 p0 = __ldg(&g_edges[e]);
        int2 p1 = __ldg(&g_edges[e + 1]);
        int2 p2 = __ldg(&g_edges[e + 2]);
        int2 p3 = __ldg(&g_edges[e + 3]);
        uint32_t u0 = __ldg(reinterpret_cast<const uint32_t*>(Y + (size_t)p0.x * 64) + lane);
        uint32_t u1 = __ldg(reinterpret_cast<const uint32_t*>(Y + (size_t)p1.x * 64) + lane);
        uint32_t u2 = __ldg(reinterpret_cast<const uint32_t*>(Y + (size_t)p2.x * 64) + lane);
        uint32_t u3 = __ldg(reinterpret_cast<const uint32_t*>(Y + (size_t)p3.x * 64) + lane);
        float v0 = __int_as_float(p0.y), v1 = __int_as_float(p1.y);
        float v2 = __int_as_float(p2.y), v3 = __int_as_float(p3.y);
        float2 f0 = __half22float2(*reinterpret_cast<__half2*>(&u0));
        float2 f1 = __half22float2(*reinterpret_cast<__half2*>(&u1));
        float2 f2 = __half22float2(*reinterpret_cast<__half2*>(&u2));
        float2 f3 = __half22float2(*reinterpret_cast<__half2*>(&u3));
        acc.x = fmaf(v0, f0.x, acc.x); acc.y = fmaf(v0, f0.y, acc.y);
        acc.x = fmaf(v1, f1.x, acc.x); acc.y = fmaf(v1, f1.y, acc.y);
        acc.x = fmaf(v2, f2.x, acc.x); acc.y = fmaf(v2, f2.y, acc.y);
        acc.x = fmaf(v3, f3.x, acc.x); acc.y = fmaf(v3, f3.y, acc.y);
    }
    for (; e < end; ++e) {
        int2 p = __ldg(&g_edges[e]);
        float v = __int_as_float(p.y);
        uint32_t u = __ldg(reinterpret_cast<const uint32_t*>(Y + (size_t)p.x * 64) + lane);
        float2 f = __half22float2(*reinterpret_cast<__half2*>(&u));
        acc.x = fmaf(v, f.x, acc.x); acc.y = fmaf(v, f.y, acc.y);
    }

    float m = fmaxf(acc.x, acc.y);
#pragma unroll
    for (int o = 16; o; o >>= 1) m = fmaxf(m, __shfl_xor_sync(0xffffffffu, m, o));
    float e0 = __expf(acc.x - m);
    float e1 = __expf(acc.y - m);
    float ssum = e0 + e1;
#pragma unroll
    for (int o = 16; o; o >>= 1) ssum += __shfl_xor_sync(0xffffffffu, ssum, o);
    float inv = 1.f / ssum;
    *reinterpret_cast<float2*>(out + (size_t)d * 64 + lane * 2) =
        make_float2(e0 * inv, e1 * inv);
}

// ---------------------------------------------------------------------------
// Launch. Inputs: x, vals, W1, W2, src, dst. Output fp32 [N, 64].
// Slot 5 = gemm128 (ncu capture).
// ---------------------------------------------------------------------------
extern "C" void kernel_launch(void* const* d_in, const int* in_sizes, int n_in,
                              void* d_out, int out_size)
{
    const float* x    = (const float*)d_in[0];
    const float* vals = (const float*)d_in[1];
    const float* W1   = (const float*)d_in[2];
    const float* W2   = (const float*)d_in[3];
    const int*   src  = (const int*)d_in[4];
    const int*   dst  = (const int*)d_in[5];
    float*       out  = (float*)d_out;

    const int M = in_sizes[0] / NF;   // 50000
    const int E = in_sizes[1];        // 800000

    __half *y1h, *y2h;
    float* s1;
    int* degp;
    cudaGetSymbolAddress((void**)&y1h, g_y1h);
    cudaGetSymbolAddress((void**)&s1, g_s1);
    cudaGetSymbolAddress((void**)&y2h, g_y2h);
    cudaGetSymbolAddress((void**)&degp, g_deg);

    const int nb = (M + SCAN_B - 1) / SCAN_B;           // 98
    const int gemmBlocks = (M + 127) / 128;

    cudaMemsetAsync(degp, 0, M * sizeof(int));                              // 1
    hist_kernel<<<(E + 255) / 256, 256>>>(dst, E);                          // 2
    scan1_kernel<<<nb, SCAN_B>>>(M);                                        // 3
    scan23_kernel<<<(M + 255) / 256, 256>>>(M, nb, E);                      // 4
    gemm_tc_kernel<128, false><<<gemmBlocks, 256>>>(x, W1, y1h, M);         // 5 (ncu slot)
    permute_kernel<<<(E + 255) / 256, 256>>>(src, dst, vals, E);            // 6
    gather128_kernel<<<(M * 32 + 255) / 256, 256>>>(y1h, s1, M);            // 7
    gemm_tc_kernel<64, true><<<gemmBlocks, 256>>>(s1, W2, y2h, M);          // 8
    gather64_softmax_kernel<<<(M * 32 + 255) / 256, 256>>>(y2h, out, M);    // 9
}

// round 14
// speedup vs baseline: 2.0730x; 1.0857x over previous
#include <cuda_runtime.h>
#include <cuda_fp16.h>
#include <cstdint>
#include <cstddef>

#define MAXN 50000
#define MAXE 800000
#define NF   128
#define NOUT 64
#define SCAN_B 512

// Scratch (no allocations allowed -> __device__ globals).
__device__ uint2 g_y1h[(size_t)MAXN * NF / 4];    // x @ W1^T            (half)
__device__ float g_s1[(size_t)MAXN * NF];         // gather-spmm(y1)     (fp32)
__device__ uint2 g_y2h[(size_t)MAXN * NOUT / 4];  // relu(s1) @ W2^T     (half)
__device__ int   g_deg[MAXN];                     // degree counts, then write-cursor
__device__ int   g_off[MAXN + 1];                 // CSR row offsets (by dst)
__device__ int   g_bsum[SCAN_B];                  // scan block sums
__device__ int2  g_edges[MAXE];                   // {src, __float_as_int(val)} by dst

// ---------------------------------------------------------------------------
// CSR build: histogram -> scan1 (per-block) -> scan23 (apply) -> permute
// ---------------------------------------------------------------------------
__global__ void hist_kernel(const int* __restrict__ dst, int E) {
    int i = blockIdx.x * blockDim.x + threadIdx.x;
    if (i < E) atomicAdd(&g_deg[__ldg(dst + i)], 1);
}

__global__ __launch_bounds__(SCAN_B) void scan1_kernel(int n) {
    __shared__ int sh[SCAN_B];
    int t = threadIdx.x;
    int i = blockIdx.x * SCAN_B + t;
    int v = (i < n) ? g_deg[i] : 0;
    sh[t] = v;
    __syncthreads();
#pragma unroll
    for (int o = 1; o < SCAN_B; o <<= 1) {
        int u = (t >= o) ? sh[t - o] : 0;
        __syncthreads();
        sh[t] += u;
        __syncthreads();
    }
    if (i <= n && i < MAXN + 1) g_off[i] = sh[t] - v;
    if (t == SCAN_B - 1) g_bsum[blockIdx.x] = sh[t];
}

__global__ void scan23_kernel(int n, int nb, int E) {
    __shared__ int pref[256];
    int t = threadIdx.x;
    if (t == 0) {
        int run = 0;
        for (int b = 0; b < nb; ++b) { pref[b] = run; run += g_bsum[b]; }
    }
    __syncthreads();
    int i = blockIdx.x * blockDim.x + t;
    if (i < n) {
        int o = g_off[i] + pref[i >> 9];
        g_off[i] = o;
        g_deg[i] = o;
    }
    if (i == 0) g_off[n] = E;
}

__global__ void permute_kernel(const int* __restrict__ src, const int* __restrict__ dst,
                               const float* __restrict__ vals, int E) {
    int e = blockIdx.x * blockDim.x + threadIdx.x;
    if (e >= E) return;
    int pos = atomicAdd(&g_deg[__ldg(dst + e)], 1);
    g_edges[pos] = make_int2(__ldg(src + e), __float_as_int(__ldg(vals + e)));
}

// ---------------------------------------------------------------------------
// bf16 / mma / ldmatrix helpers
// ---------------------------------------------------------------------------
__device__ __forceinline__ uint32_t bf16x2_rn(float f0, float f1) {
    uint32_t r;
    asm("cvt.rn.bf16x2.f32 %0, %1, %2;" : "=r"(r) : "f"(f1), "f"(f0));
    return r;
}

template <bool RELU>
__device__ __forceinline__ void cvt8_bf(const float* v, uint32_t* hw, uint32_t* lw) {
#pragma unroll
    for (int p = 0; p < 4; ++p) {
        float f0 = v[2 * p], f1 = v[2 * p + 1];
        if (RELU) { f0 = fmaxf(f0, 0.f); f1 = fmaxf(f1, 0.f); }
        uint32_t h = bf16x2_rn(f0, f1);
        float h0 = __uint_as_float(h << 16);
        float h1 = __uint_as_float(h & 0xFFFF0000u);
        uint32_t l = bf16x2_rn(f0 - h0, f1 - h1);
        hw[p] = h; lw[p] = l;
    }
}

__device__ __forceinline__ void mma_bf16(float* d, const uint32_t* a, uint32_t b0, uint32_t b1) {
    asm volatile(
        "mma.sync.aligned.m16n8k16.row.col.f32.bf16.bf16.f32 "
        "{%0,%1,%2,%3}, {%4,%5,%6,%7}, {%8,%9}, {%0,%1,%2,%3};"
        : "+f"(d[0]), "+f"(d[1]), "+f"(d[2]), "+f"(d[3])
        : "r"(a[0]), "r"(a[1]), "r"(a[2]), "r"(a[3]), "r"(b0), "r"(b1));
}

__device__ __forceinline__ void ldm_x4(uint32_t* r, uint32_t saddr) {
    asm volatile("ldmatrix.sync.aligned.m8n8.x4.shared.b16 {%0,%1,%2,%3}, [%4];"
                 : "=r"(r[0]), "=r"(r[1]), "=r"(r[2]), "=r"(r[3]) : "r"(saddr));
}

// ---------------------------------------------------------------------------
// C[M, NCOLS] (fp16) = act(A fp32)[M, 128] @ W[NCOLS, 128]^T via 3xBF16 MMA.
// ---------------------------------------------------------------------------
template <int NCOLS, bool RELU_IN>
__global__ __launch_bounds__(256) void gemm_tc_kernel(
    const float* __restrict__ A, const float* __restrict__ W,
    __half* __restrict__ C, int M)
{
    constexpr int BK   = 32;
    constexpr int STRD = 20;
    constexpr int NT   = NCOLS / 16;

    __shared__ __align__(16) uint32_t As_hi[128 * STRD];
    __shared__ __align__(16) uint32_t As_lo[128 * STRD];
    __shared__ __align__(16) uint32_t Bs_hi[NCOLS * STRD];
    __shared__ __align__(16) uint32_t Bs_lo[NCOLS * STRD];

    const int tid  = threadIdx.x;
    const int wid  = tid >> 5;
    const int lane = tid & 31;
    const int g    = lane >> 2;
    const int t    = lane & 3;
    const int warp_m = wid >> 1;
    const int warp_n = wid & 1;
    const int blockRow = blockIdx.x * 128;

    float acc[2][NT][4];
#pragma unroll
    for (int mt = 0; mt < 2; ++mt)
#pragma unroll
        for (int nt = 0; nt < NT; ++nt)
#pragma unroll
            for (int i = 0; i < 4; ++i) acc[mt][nt][i] = 0.f;

    const uint32_t sAhi = (uint32_t)__cvta_generic_to_shared(As_hi);
    const uint32_t sAlo = (uint32_t)__cvta_generic_to_shared(As_lo);
    const uint32_t sBhi = (uint32_t)__cvta_generic_to_shared(Bs_hi);
    const uint32_t sBlo = (uint32_t)__cvta_generic_to_shared(Bs_lo);

    const int  arow  = tid >> 1;
    const int  akoff = (tid & 1) * 16;
    const int  gArow = blockRow + arow;
    const bool aok   = (gArow < M);

    const int a_lr = lane & 15;
    const int a_kb = (lane >> 4) * 16;
    const int b_lr = (lane & 7) + ((lane >> 4) << 3);
    const int b_kb = ((lane >> 3) & 1) * 16;

    for (int k0 = 0; k0 < 128; k0 += BK) {
        {
            float v[16];
#pragma unroll
            for (int j = 0; j < 16; ++j) v[j] = 0.f;
            if (aok) {
                const float* ap = A + (size_t)gArow * 128 + k0 + akoff;
                *reinterpret_cast<float4*>(v)      = *reinterpret_cast<const float4*>(ap);
                *reinterpret_cast<float4*>(v + 4)  = *reinterpret_cast<const float4*>(ap + 4);
                *reinterpret_cast<float4*>(v + 8)  = *reinterpret_cast<const float4*>(ap + 8);
                *reinterpret_cast<float4*>(v + 12) = *reinterpret_cast<const float4*>(ap + 12);
            }
            uint32_t hw[8], lw[8];
            cvt8_bf<RELU_IN>(v, hw, lw);
            cvt8_bf<RELU_IN>(v + 8, hw + 4, lw + 4);
            int wo = arow * STRD + (akoff >> 1);
            *reinterpret_cast<uint4*>(&As_hi[wo])     = make_uint4(hw[0], hw[1], hw[2], hw[3]);
            *reinterpret_cast<uint4*>(&As_hi[wo + 4]) = make_uint4(hw[4], hw[5], hw[6], hw[7]);
            *reinterpret_cast<uint4*>(&As_lo[wo])     = make_uint4(lw[0], lw[1], lw[2], lw[3]);
            *reinterpret_cast<uint4*>(&As_lo[wo + 4]) = make_uint4(lw[4], lw[5], lw[6], lw[7]);
        }
        if (NCOLS == 128) {
            int brow  = tid >> 1;
            int bkoff = (tid & 1) * 16;
            float v[16];
            const float* wp = W + (size_t)brow * 128 + k0 + bkoff;
            *reinterpret_cast<float4*>(v)      = *reinterpret_cast<const float4*>(wp);
            *reinterpret_cast<float4*>(v + 4)  = *reinterpret_cast<const float4*>(wp + 4);
            *reinterpret_cast<float4*>(v + 8)  = *reinterpret_cast<const float4*>(wp + 8);
            *reinterpret_cast<float4*>(v + 12) = *reinterpret_cast<const float4*>(wp + 12);
            uint32_t hw[8], lw[8];
            cvt8_bf<false>(v, hw, lw);
            cvt8_bf<false>(v + 8, hw + 4, lw + 4);
            int wo = brow * STRD + (bkoff >> 1);
            *reinterpret_cast<uint4*>(&Bs_hi[wo])     = make_uint4(hw[0], hw[1], hw[2], hw[3]);
            *reinterpret_cast<uint4*>(&Bs_hi[wo + 4]) = make_uint4(hw[4], hw[5], hw[6], hw[7]);
            *reinterpret_cast<uint4*>(&Bs_lo[wo])     = make_uint4(lw[0], lw[1], lw[2], lw[3]);
            *reinterpret_cast<uint4*>(&Bs_lo[wo + 4]) = make_uint4(lw[4], lw[5], lw[6], lw[7]);
        } else {
            int brow  = tid >> 2;
            int bkoff = (tid & 3) * 8;
            float v[8];
            const float* wp = W + (size_t)brow * 128 + k0 + bkoff;
            *reinterpret_cast<float4*>(v)     = *reinterpret_cast<const float4*>(wp);
            *reinterpret_cast<float4*>(v + 4) = *reinterpret_cast<const float4*>(wp + 4);
            uint32_t hw[4], lw[4];
            cvt8_bf<false>(v, hw, lw);
            int wo = brow * STRD + (bkoff >> 1);
            *reinterpret_cast<uint4*>(&Bs_hi[wo]) = make_uint4(hw[0], hw[1], hw[2], hw[3]);
            *reinterpret_cast<uint4*>(&Bs_lo[wo]) = make_uint4(lw[0], lw[1], lw[2], lw[3]);
        }
        __syncthreads();

#pragma unroll
        for (int ks = 0; ks < 2; ++ks) {
            const int kbyte = ks * 32;
            uint32_t ah[2][4], al[2][4];
#pragma unroll
            for (int mt = 0; mt < 2; ++mt) {
                uint32_t off = (uint32_t)((warp_m * 32 + mt * 16 + a_lr) * STRD) * 4u + kbyte + a_kb;
                ldm_x4(ah[mt], sAhi + off);
                ldm_x4(al[mt], sAlo + off);
            }
#pragma unroll
            for (int ntp = 0; ntp < NT / 2; ++ntp) {
                int nbase = warp_n * (NCOLS / 2) + ntp * 16;
                uint32_t off = (uint32_t)((nbase + b_lr) * STRD) * 4u + kbyte + b_kb;
                uint32_t bh[4], bl[4];
                ldm_x4(bh, sBhi + off);
                ldm_x4(bl, sBlo + off);
#pragma unroll
                for (int mt = 0; mt < 2; ++mt) {
                    mma_bf16(acc[mt][2 * ntp],     ah[mt], bh[0], bh[1]);
                    mma_bf16(acc[mt][2 * ntp],     ah[mt], bl[0], bl[1]);
                    mma_bf16(acc[mt][2 * ntp],     al[mt], bh[0], bh[1]);
                    mma_bf16(acc[mt][2 * ntp + 1], ah[mt], bh[2], bh[3]);
                    mma_bf16(acc[mt][2 * ntp + 1], ah[mt], bl[2], bl[3]);
                    mma_bf16(acc[mt][2 * ntp + 1], al[mt], bh[2], bh[3]);
                }
            }
        }
        __syncthreads();
    }

#pragma unroll
    for (int mt = 0; mt < 2; ++mt) {
#pragma unroll
        for (int half = 0; half < 2; ++half) {
            int row = blockRow + warp_m * 32 + mt * 16 + half * 8 + g;
            if (row < M) {
#pragma unroll
                for (int nt = 0; nt < NT; ++nt) {
                    int col = warp_n * (NCOLS / 2) + nt * 8 + 2 * t;
                    __half2 h = __float22half2_rn(
                        make_float2(acc[mt][nt][half * 2], acc[mt][nt][half * 2 + 1]));
                    *reinterpret_cast<__half2*>(C + (size_t)row * NCOLS + col) = h;
                }
            }
        }
    }
}

// ---------------------------------------------------------------------------
// Gather SPMM, 128-wide fp16 input: warp/node, 4 halfs/lane, fp32 accumulate.
// ---------------------------------------------------------------------------
__global__ __launch_bounds__(256) void gather128_kernel(
    const __half* __restrict__ Y, float* __restrict__ S, int n)
{
    int gid  = blockIdx.x * blockDim.x + threadIdx.x;
    int d    = gid >> 5;
    int lane = threadIdx.x & 31;
    if (d >= n) return;
    int beg = g_off[d], end = g_off[d + 1];

    float4 acc = make_float4(0.f, 0.f, 0.f, 0.f);
    int e = beg;
    for (; e + 3 < end; e += 4) {
        int2 p0 = __ldg(&g_edges[e]);
        int2 p1 = __ldg(&g_edges[e + 1]);
        int2 p2 = __ldg(&g_edges[e + 2]);
        int2 p3 = __ldg(&g_edges[e + 3]);
        uint2 u0 = __ldg(reinterpret_cast<const uint2*>(Y + (size_t)p0.x * 128) + lane);
        uint2 u1 = __ldg(reinterpret_cast<const uint2*>(Y + (size_t)p1.x * 128) + lane);
        uint2 u2 = __ldg(reinterpret_cast<const uint2*>(Y + (size_t)p2.x * 128) + lane);
        uint2 u3 = __ldg(reinterpret_cast<const uint2*>(Y + (size_t)p3.x * 128) + lane);
        float v0 = __int_as_float(p0.y), v1 = __int_as_float(p1.y);
        float v2 = __int_as_float(p2.y), v3 = __int_as_float(p3.y);
        float2 a0 = __half22float2(*reinterpret_cast<__half2*>(&u0.x));
        float2 b0 = __half22float2(*reinterpret_cast<__half2*>(&u0.y));
        float2 a1 = __half22float2(*reinterpret_cast<__half2*>(&u1.x));
        float2 b1 = __half22float2(*reinterpret_cast<__half2*>(&u1.y));
        float2 a2 = __half22float2(*reinterpret_cast<__half2*>(&u2.x));
        float2 b2 = __half22float2(*reinterpret_cast<__half2*>(&u2.y));
        float2 a3 = __half22float2(*reinterpret_cast<__half2*>(&u3.x));
        float2 b3 = __half22float2(*reinterpret_cast<__half2*>(&u3.y));
        acc.x = fmaf(v0, a0.x, acc.x); acc.y = fmaf(v0, a0.y, acc.y);
        acc.z = fmaf(v0, b0.x, acc.z); acc.w = fmaf(v0, b0.y, acc.w);
        acc.x = fmaf(v1, a1.x, acc.x); acc.y = fmaf(v1, a1.y, acc.y);
        acc.z = fmaf(v1, b1.x, acc.z); acc.w = fmaf(v1, b1.y, acc.w);
        acc.x = fmaf(v2, a2.x, acc.x); acc.y = fmaf(v2, a2.y, acc.y);
        acc.z = fmaf(v2, b2.x, acc.z); acc.w = fmaf(v2, b2.y, acc.w);
        acc.x = fmaf(v3, a3.x, acc.x); acc.y = fmaf(v3, a3.y, acc.y);
        acc.z = fmaf(v3, b3.x, acc.z); acc.w = fmaf(v3, b3.y, acc.w);
    }
    for (; e < end; ++e) {
        int2 p = __ldg(&g_edges[e]);
        float v = __int_as_float(p.y);
        uint2 u = __ldg(reinterpret_cast<const uint2*>(Y + (size_t)p.x * 128) + lane);
        float2 a = __half22float2(*reinterpret_cast<__half2*>(&u.x));
        float2 b = __half22float2(*reinterpret_cast<__half2*>(&u.y));
        acc.x = fmaf(v, a.x, acc.x); acc.y = fmaf(v, a.y, acc.y);
        acc.z = fmaf(v, b.x, acc.z); acc.w = fmaf(v, b.y, acc.w);
    }
    *reinterpret_cast<float4*>(S + (size_t)d * 128 + lane * 4) = acc;
}

// ---------------------------------------------------------------------------
// Gather SPMM, 64-wide fp16 input, fused row softmax: warp/node, 2 halfs/lane.
// ---------------------------------------------------------------------------
__global__ __launch_bounds__(256) void gather64_softmax_kernel(
    const __half* __restrict__ Y, float* __restrict__ out, int n)
{
    int gid  = blockIdx.x * blockDim.x + threadIdx.x;
    int d    = gid >> 5;
    int lane = threadIdx.x & 31;
    if (d >= n) return;
    int beg = g_off[d], end = g_off[d + 1];

    float2 acc = make_float2(0.f, 0.f);
    int e = beg;
    for (; e + 3 < end; e += 4) {
        int2 p0 = __ldg(&g_edges[e]);
        int2 p1 = __ldg(&g_edges[e + 1]);
        int2 p2 = __ldg(&g_edges[e + 2]);
        int2 p3 = __ldg(&g_edges[e + 3]);
        uint32_t u0 = __ldg(reinterpret_cast<const uint32_t*>(Y + (size_t)p0.x * 64) + lane);
        uint32_t u1 = __ldg(reinterpret_cast<const uint32_t*>(Y + (size_t)p1.x * 64) + lane);
        uint32_t u2 = __ldg(reinterpret_cast<const uint32_t*>(Y + (size_t)p2.x * 64) + lane);
        uint32_t u3 = __ldg(reinterpret_cast<const uint32_t*>(Y + (size_t)p3.x * 64) + lane);
        float v0 = __int_as_float(p0.y), v1 = __int_as_float(p1.y);
        float v2 = __int_as_float(p2.y), v3 = __int_as_float(p3.y);
        float2 f0 = __half22float2(*reinterpret_cast<__half2*>(&u0));
        float2 f1 = __half22float2(*reinterpret_cast<__half2*>(&u1));
        float2 f2 = __half22float2(*reinterpret_cast<__half2*>(&u2));
        float2 f3 = __half22float2(*reinterpret_cast<__half2*>(&u3));
        acc.x = fmaf(v0, f0.x, acc.x); acc.y = fmaf(v0, f0.y, acc.y);
        acc.x = fmaf(v1, f1.x, acc.x); acc.y = fmaf(v1, f1.y, acc.y);
        acc.x = fmaf(v2, f2.x, acc.x); acc.y = fmaf(v2, f2.y, acc.y);
        acc.x = fmaf(v3, f3.x, acc.x); acc.y = fmaf(v3, f3.y, acc.y);
    }
    for (; e < end; ++e) {
        int2 p = __ldg(&g_edges[e]);
        float v = __int_as_float(p.y);
        uint32_t u = __ldg(reinterpret_cast<const uint32_t*>(Y + (size_t)p.x * 64) + lane);
        float2 f = __half22float2(*reinterpret_cast<__half2*>(&u));
        acc.x = fmaf(v, f.x, acc.x); acc.y = fmaf(v, f.y, acc.y);
    }

    float m = fmaxf(acc.x, acc.y);
#pragma unroll
    for (int o = 16; o; o >>= 1) m = fmaxf(m, __shfl_xor_sync(0xffffffffu, m, o));
    float e0 = __expf(acc.x - m);
    float e1 = __expf(acc.y - m);
    float ssum = e0 + e1;
#pragma unroll
    for (int o = 16; o; o >>= 1) ssum += __shfl_xor_sync(0xffffffffu, ssum, o);
    float inv = 1.f / ssum;
    *reinterpret_cast<float2*>(out + (size_t)d * 64 + lane * 2) =
        make_float2(e0 * inv, e1 * inv);
}

// ---------------------------------------------------------------------------
// Launch. Inputs: x, vals, W1, W2, src, dst. Output fp32 [N, 64].
// gemm128 runs on a forked stream, overlapping the whole CSR build chain;
// fork/join via events is the standard multi-stream graph-capture pattern.
// Submission order keeps gemm128 as the 5th launch (ncu capture slot).
// ---------------------------------------------------------------------------
extern "C" void kernel_launch(void* const* d_in, const int* in_sizes, int n_in,
                              void* d_out, int out_size)
{
    const float* x    = (const float*)d_in[0];
    const float* vals = (const float*)d_in[1];
    const float* W1   = (const float*)d_in[2];
    const float* W2   = (const float*)d_in[3];
    const int*   src  = (const int*)d_in[4];
    const int*   dst  = (const int*)d_in[5];
    float*       out  = (float*)d_out;

    const int M = in_sizes[0] / NF;   // 50000
    const int E = in_sizes[1];        // 800000

    __half *y1h, *y2h;
    float* s1;
    int* degp;
    cudaGetSymbolAddress((void**)&y1h, g_y1h);
    cudaGetSymbolAddress((void**)&s1, g_s1);
    cudaGetSymbolAddress((void**)&y2h, g_y2h);
    cudaGetSymbolAddress((void**)&degp, g_deg);

    const int nb = (M + SCAN_B - 1) / SCAN_B;           // 98
    const int gemmBlocks = (M + 127) / 128;

    // Fork a side stream for the gemm128 chain (independent of CSR build).
    cudaStream_t s2;
    cudaEvent_t evFork, evJoin;
    cudaStreamCreateWithFlags(&s2, cudaStreamNonBlocking);
    cudaEventCreateWithFlags(&evFork, cudaEventDisableTiming);
    cudaEventCreateWithFlags(&evJoin, cudaEventDisableTiming);

    cudaEventRecord(evFork, 0);
    cudaStreamWaitEvent(s2, evFork, 0);

    // --- chain A (CSR build) on the default stream ---
    cudaMemsetAsync(degp, 0, M * sizeof(int));                              // 1
    hist_kernel<<<(E + 255) / 256, 256>>>(dst, E);                          // 2
    scan1_kernel<<<nb, SCAN_B>>>(M);                                        // 3
    scan23_kernel<<<(M + 255) / 256, 256>>>(M, nb, E);                      // 4
    // --- chain B (gemm128) on s2; submitted 5th for the ncu slot ---
    gemm_tc_kernel<128, false><<<gemmBlocks, 256, 0, s2>>>(x, W1, y1h, M);  // 5 (ncu slot)
    cudaEventRecord(evJoin, s2);
    permute_kernel<<<(E + 255) / 256, 256>>>(src, dst, vals, E);            // 6

    // --- join: gather128 needs both chains ---
    cudaStreamWaitEvent(0, evJoin, 0);
    gather128_kernel<<<(M * 32 + 255) / 256, 256>>>(y1h, s1, M);            // 7
    gemm_tc_kernel<64, true><<<gemmBlocks, 256>>>(s1, W2, y2h, M);          // 8
    gather64_softmax_kernel<<<(M * 32 + 255) / 256, 256>>>(y2h, out, M);    // 9
}